// round 8
// baseline (speedup 1.0000x reference)
#include <cuda_runtime.h>
#include <cuda_bf16.h>
#include <math.h>
#include <stdint.h>

#define Dd   1024
#define Ls   4096
#define NTOK 8192
#define HDd  64
#define WINs 256
#define Gg   2
#define Hh   16
#define Ee   8
#define HIDs 1024
#define QKVW 1280      // 1024 q + 128 k + 128 v
#define STRD 40        // padded bf16 row stride in gemm smem tiles
#define STAGEB 40960   // bytes per gemm pipeline stage
#define AQS  72        // attn smem row stride (bf16 elems)

typedef __nv_bfloat16 bf;
typedef __nv_bfloat162 bf2;

// ---------------- device scratch --------------------------------------------
__device__ float g_qkv[NTOK * QKVW];                 // fused q|k|v fp32
__device__ bf    g_ah[NTOK * Dd], g_al[NTOK * Dd];   // ln1 hi/lo
__device__ bf    g_oh[NTOK * Dd], g_ol[NTOK * Dd];   // attn out hi/lo
__device__ float g_ln2[NTOK * Dd];
__device__ bf    g_2h[NTOK * Dd], g_2l[NTOK * Dd];   // ln2 hi/lo
__device__ bf    g_wh[QKVW * Dd], g_wl[QKVW * Dd];   // [Wq;Wk;Wv]^T hi/lo
__device__ bf    g_woh[Dd * Dd],  g_wol[Dd * Dd];
__device__ bf    g_weh[Ee * HIDs * Dd], g_wel[Ee * HIDs * Dd];
__device__ float g_bqkv[QKVW];
__device__ float g_part[2 * NTOK * HIDs];
__device__ int   g_cnt[Ee];
__device__ int   g_list[Ee][NTOK];
__device__ float g_wl2[Ee][NTOK];
__device__ float g_entsum;

// ---------------- helpers ---------------------------------------------------
__device__ __forceinline__ uint32_t s2u(const void* p) {
    uint32_t a;
    asm("{ .reg .u64 t; cvta.to.shared.u64 t, %1; cvt.u32.u64 %0, t; }"
        : "=r"(a) : "l"(p));
    return a;
}
__device__ __forceinline__ void ldsm4(uint32_t* r, uint32_t addr) {
    asm volatile("ldmatrix.sync.aligned.m8n8.x4.shared.b16 {%0,%1,%2,%3}, [%4];"
                 : "=r"(r[0]), "=r"(r[1]), "=r"(r[2]), "=r"(r[3]) : "r"(addr));
}
__device__ __forceinline__ void ldsm4t(uint32_t* r, uint32_t addr) {
    asm volatile("ldmatrix.sync.aligned.m8n8.x4.trans.shared.b16 {%0,%1,%2,%3}, [%4];"
                 : "=r"(r[0]), "=r"(r[1]), "=r"(r[2]), "=r"(r[3]) : "r"(addr));
}
__device__ __forceinline__ void mma16816(float* c, const uint32_t* a, const uint32_t* b) {
    asm volatile(
        "mma.sync.aligned.m16n8k16.row.col.f32.bf16.bf16.f32 "
        "{%0,%1,%2,%3}, {%4,%5,%6,%7}, {%8,%9}, {%0,%1,%2,%3};"
        : "+f"(c[0]), "+f"(c[1]), "+f"(c[2]), "+f"(c[3])
        : "r"(a[0]), "r"(a[1]), "r"(a[2]), "r"(a[3]), "r"(b[0]), "r"(b[1]));
}
__device__ __forceinline__ void cpa16(uint32_t dst, const void* src) {
    asm volatile("cp.async.cg.shared.global [%0], [%1], 16;" :: "r"(dst), "l"(src));
}
__device__ __forceinline__ uint32_t packbf(float a, float b) {
    bf2 t = __halves2bfloat162(__float2bfloat16(a), __float2bfloat16(b));
    return *(uint32_t*)&t;
}

// ---------------- init / bias concat ----------------------------------------
__global__ void init_kernel() {
    int t = threadIdx.x;
    if (t < Ee) g_cnt[t] = 0;
    if (t == 0) g_entsum = 0.f;
}
__global__ void catb_a(const float* bq) {
    int i = blockIdx.x * 256 + threadIdx.x;
    g_bqkv[i] = bq[i];
}
__global__ void catb_b(const float* bk, const float* bv) {
    int t = threadIdx.x;
    if (t < 128) g_bqkv[1024 + t] = bk[t];
    else g_bqkv[1024 + t] = bv[t - 128];
}

// ---------------- layernorm with hi/lo emit ---------------------------------
__device__ __forceinline__ float brsum(float v, float* sh) {
    int lane = threadIdx.x & 31, w = threadIdx.x >> 5;
    #pragma unroll
    for (int o = 16; o; o >>= 1) v += __shfl_xor_sync(0xffffffffu, v, o);
    if (lane == 0) sh[w] = v;
    __syncthreads();
    if (w == 0) {
        float r = (lane < 8) ? sh[lane] : 0.f;
        #pragma unroll
        for (int o = 4; o; o >>= 1) r += __shfl_xor_sync(0xffffffffu, r, o);
        if (lane == 0) sh[0] = r;
    }
    __syncthreads();
    float r = sh[0];
    __syncthreads();
    return r;
}

__global__ __launch_bounds__(256) void ln_kernel(
    const float* __restrict__ x, const float* __restrict__ g,
    const float* __restrict__ b, float* __restrict__ outf,
    bf* __restrict__ oh, bf* __restrict__ ol)
{
    __shared__ float sh[8];
    size_t row = blockIdx.x;
    int tid = threadIdx.x;
    float4 v = ((const float4*)(x + row * Dd))[tid];
    float mean = brsum(v.x + v.y + v.z + v.w, sh) * (1.f / Dd);
    float d0 = v.x - mean, d1 = v.y - mean, d2 = v.z - mean, d3 = v.w - mean;
    float var = brsum(d0*d0 + d1*d1 + d2*d2 + d3*d3, sh) * (1.f / Dd);
    float inv = rsqrtf(var + 1e-5f);
    float4 gv = ((const float4*)g)[tid];
    float4 bv = ((const float4*)b)[tid];
    float o0 = d0*inv*gv.x + bv.x, o1 = d1*inv*gv.y + bv.y;
    float o2 = d2*inv*gv.z + bv.z, o3 = d3*inv*gv.w + bv.w;
    if (outf) ((float4*)(outf + row * Dd))[tid] = make_float4(o0, o1, o2, o3);
    bf h0 = __float2bfloat16(o0), h1 = __float2bfloat16(o1);
    bf h2 = __float2bfloat16(o2), h3 = __float2bfloat16(o3);
    bf2* hp = (bf2*)(oh + row * Dd);
    hp[2*tid]   = __halves2bfloat162(h0, h1);
    hp[2*tid+1] = __halves2bfloat162(h2, h3);
    bf2* lp = (bf2*)(ol + row * Dd);
    lp[2*tid]   = __halves2bfloat162(__float2bfloat16(o0 - __bfloat162float(h0)),
                                     __float2bfloat16(o1 - __bfloat162float(h1)));
    lp[2*tid+1] = __halves2bfloat162(__float2bfloat16(o2 - __bfloat162float(h2)),
                                     __float2bfloat16(o3 - __bfloat162float(h3)));
}

// ---------------- merged weight transpose + split ---------------------------
// z=0: Wq  z=1: Wk  z=2: Wv  z=3: Wo  z=4..11: We[e]
__global__ __launch_bounds__(256) void tconv_all(
    const float* __restrict__ Wq, const float* __restrict__ Wk,
    const float* __restrict__ Wv, const float* __restrict__ Wo,
    const float* __restrict__ We)
{
    __shared__ float t[32][33];
    int z = blockIdx.z;
    const float* W; bf *Th, *Tl; int Nc;
    if (z == 0)      { W = Wq; Th = g_wh; Tl = g_wl; Nc = 1024; }
    else if (z == 1) { W = Wk; Th = g_wh + (size_t)1024*Dd; Tl = g_wl + (size_t)1024*Dd; Nc = 128; }
    else if (z == 2) { W = Wv; Th = g_wh + (size_t)1152*Dd; Tl = g_wl + (size_t)1152*Dd; Nc = 128; }
    else if (z == 3) { W = Wo; Th = g_woh; Tl = g_wol; Nc = 1024; }
    else {
        int e = z - 4;
        W = We + (size_t)e * Dd * HIDs;
        Th = g_weh + (size_t)e * Dd * HIDs; Tl = g_wel + (size_t)e * Dd * HIDs;
        Nc = 1024;
    }
    int n0 = blockIdx.x * 32;
    if (n0 >= Nc) return;
    int k0 = blockIdx.y * 32;
    int tx = threadIdx.x & 31, ty = threadIdx.x >> 5;
    #pragma unroll
    for (int r = 0; r < 4; r++)
        t[ty + 8*r][tx] = W[(size_t)(k0 + ty + 8*r) * Nc + n0 + tx];
    __syncthreads();
    #pragma unroll
    for (int r = 0; r < 4; r++) {
        float v = t[tx][ty + 8*r];
        size_t o = (size_t)(n0 + ty + 8*r) * Dd + k0 + tx;
        bf h = __float2bfloat16(v);
        Th[o] = h;
        Tl[o] = __float2bfloat16(v - __bfloat162float(h));
    }
}

// ---------------- HMMA split-bf16 GEMM, 4-stage cp.async pipeline -----------
__global__ __launch_bounds__(256, 1) void gemm_mma(
    const bf* __restrict__ Ahi, const bf* __restrict__ Alo,
    const bf* __restrict__ Bhi, const bf* __restrict__ Blo,
    const float* __restrict__ bias, const float* __restrict__ res,
    float* __restrict__ C, int zRow, int ldc, int mode)
{
    extern __shared__ bf sm[];
    __shared__ int s_ent[128];
    __shared__ float s_w[128];
    __shared__ int s_ridx[128];

    int tid = threadIdx.x, lane = tid & 31, wid = tid >> 5;
    int n0 = blockIdx.x * 128;
    int row0 = 0, cnt = 0, m0 = 0;
    const bf *bh = Bhi, *bl = Blo;
    const float* bptr = bias;
    if (mode == 1) {
        int e = blockIdx.z;
        cnt = g_cnt[e];
        m0 = blockIdx.y * 128;
        if (m0 >= cnt) return;
        bh = Bhi + ((size_t)e << 20);
        bl = Blo + ((size_t)e << 20);
        bptr = bias + e * HIDs;
        if (tid < 128) {
            int m = m0 + tid;
            int ent = (m < cnt) ? g_list[e][m] : -1;
            s_ent[tid] = ent;
            s_ridx[tid] = (ent >= 0) ? (ent >> 1) : -1;
            s_w[tid] = (m < cnt) ? g_wl2[e][m] : 0.f;
        }
        __syncthreads();
    } else {
        row0 = blockIdx.z * zRow + blockIdx.y * 128;
    }
    const int* rp = (mode == 1) ? s_ridx : nullptr;
    uint32_t sb = s2u(sm);

    float c[4][4][4] = {};
    int wm = (wid & 1) * 64, wn = (wid >> 1) * 32;

    #define LOAD_STAGE(s, k0)                                                   \
    do {                                                                        \
        for (int i = tid; i < 2048; i += 256) {                                 \
            int part = i >> 9, r = (i >> 2) & 127, cb = (i & 3) * 8;            \
            uint32_t dst = sb + (s) * STAGEB + part * 10240 + (r * STRD + cb) * 2;\
            if (part < 2) {                                                     \
                int grow = rp ? rp[r] : (row0 + r);                             \
                if (grow < 0) continue;                                         \
                cpa16(dst, (part ? Alo : Ahi) + ((size_t)grow << 10) + (k0) + cb);\
            } else {                                                            \
                cpa16(dst, (part == 3 ? bl : bh) + ((size_t)(n0 + r) << 10) + (k0) + cb);\
            }                                                                   \
        }                                                                       \
        asm volatile("cp.async.commit_group;");                                 \
    } while (0)

    LOAD_STAGE(0, 0);
    LOAD_STAGE(1, 32);
    LOAD_STAGE(2, 64);

    for (int cc = 0; cc < 32; cc++) {
        asm volatile("cp.async.wait_group 2;");
        __syncthreads();
        if (cc < 29) LOAD_STAGE((cc + 3) & 3, (cc + 3) * 32);
        else         asm volatile("cp.async.commit_group;");

        uint32_t base = sb + (cc & 3) * STAGEB;
        #pragma unroll
        for (int ka = 0; ka < 2; ka++) {
            uint32_t a_h[4][4], a_l[4][4], b_h[4][2], b_l[4][2];
            int arow = wm + (lane & 15);
            int acol = ka * 16 + (lane >> 4) * 8;
            #pragma unroll
            for (int im = 0; im < 4; im++) {
                uint32_t ad = base + ((arow + im * 16) * STRD + acol) * 2;
                ldsm4(a_h[im], ad);
                ldsm4(a_l[im], ad + 10240);
            }
            int mtx = lane >> 3;
            int brow_off = (mtx >> 1) * 8 + (lane & 7);
            int bcol = ka * 16 + (mtx & 1) * 8;
            #pragma unroll
            for (int inb = 0; inb < 4; inb += 2) {
                uint32_t bd = base + 2 * 10240 +
                              ((wn + inb * 8 + brow_off) * STRD + bcol) * 2;
                uint32_t t4[4];
                ldsm4(t4, bd);
                b_h[inb][0] = t4[0]; b_h[inb][1] = t4[1];
                b_h[inb+1][0] = t4[2]; b_h[inb+1][1] = t4[3];
                ldsm4(t4, bd + 10240);
                b_l[inb][0] = t4[0]; b_l[inb][1] = t4[1];
                b_l[inb+1][0] = t4[2]; b_l[inb+1][1] = t4[3];
            }
            #pragma unroll
            for (int im = 0; im < 4; im++)
                #pragma unroll
                for (int in = 0; in < 4; in++) {
                    mma16816(c[im][in], a_h[im], b_h[in]);
                    mma16816(c[im][in], a_h[im], b_l[in]);
                    mma16816(c[im][in], a_l[im], b_h[in]);
                }
        }
    }

    int crow = lane >> 2, ccol = (lane & 3) * 2;
    #pragma unroll
    for (int im = 0; im < 4; im++) {
        #pragma unroll
        for (int h2 = 0; h2 < 2; h2++) {
            int r = wm + im * 16 + crow + h2 * 8;
            if (mode == 0) {
                size_t m = (size_t)(row0 + r);
                #pragma unroll
                for (int in = 0; in < 4; in++) {
                    int n = n0 + wn + in * 8 + ccol;
                    float2 v;
                    v.x = c[im][in][h2*2+0] + bptr[n];
                    v.y = c[im][in][h2*2+1] + bptr[n+1];
                    if (res) {
                        float2 q = *(const float2*)&res[m * ldc + n];
                        v.x += q.x; v.y += q.y;
                    }
                    *(float2*)&C[m * ldc + n] = v;
                }
            } else if (m0 + r < cnt) {
                int ent = s_ent[r];
                int tok = ent >> 1, slot = ent & 1;
                float w = s_w[r];
                float* dst = g_part + (((size_t)slot * NTOK + tok) << 10);
                #pragma unroll
                for (int in = 0; in < 4; in++) {
                    int n = n0 + wn + in * 8 + ccol;
                    float2 v;
                    v.x = w * (c[im][in][h2*2+0] + bptr[n]);
                    v.y = w * (c[im][in][h2*2+1] + bptr[n+1]);
                    *(float2*)&dst[n] = v;
                }
            }
        }
    }
}

// ---------------- HMMA flash attention --------------------------------------
// block = (window n, head h, batch b); 8 warps; warp owns 32 q-rows.
// Q 256x64 resident (hi/lo), K/V streamed in 4 chunks of 64 keys.
__global__ __launch_bounds__(256, 1) void attn_mma(
    const float* __restrict__ QKV, bf* __restrict__ Oh, bf* __restrict__ Ol)
{
    extern __shared__ bf smn[];
    // byte offsets: Qh 0 (36864), Ql 36864, Kh 73728 (9216), Kl 82944,
    //               Vh 92160, Vl 101376; total 110592
    bf* Qhp = smn;                bf* Qlp = smn + 18432;
    bf* Khp = smn + 36864;        bf* Klp = smn + 41472;
    bf* Vhp = smn + 46080;        bf* Vlp = smn + 50688;
    uint32_t sQ = s2u(smn);
    uint32_t sK = sQ + 73728;
    uint32_t sV = sQ + 92160;

    int n = blockIdx.x, h = blockIdx.y, b = blockIdx.z;
    int g = h & (Gg - 1);
    int kbase = n * (WINs / 2);
    int tid = threadIdx.x, lane = tid & 31, wid = tid >> 5;

    // load Q (256 rows x 64) -> hi/lo bf16
    for (int i = tid; i < 256 * 16; i += 256) {
        int r = i >> 4, c4 = (i & 15) * 4;
        float4 v = *(const float4*)(QKV + ((size_t)b*Ls + kbase + r)*QKVW + h*HDd + c4);
        int o = r * AQS + c4;
        bf h0 = __float2bfloat16(v.x), h1 = __float2bfloat16(v.y);
        bf h2 = __float2bfloat16(v.z), h3 = __float2bfloat16(v.w);
        *(bf2*)&Qhp[o]   = __halves2bfloat162(h0, h1);
        *(bf2*)&Qhp[o+2] = __halves2bfloat162(h2, h3);
        *(bf2*)&Qlp[o]   = __halves2bfloat162(__float2bfloat16(v.x - __bfloat162float(h0)),
                                              __float2bfloat16(v.y - __bfloat162float(h1)));
        *(bf2*)&Qlp[o+2] = __halves2bfloat162(__float2bfloat16(v.z - __bfloat162float(h2)),
                                              __float2bfloat16(v.w - __bfloat162float(h3)));
    }

    float o_acc[2][8][4] = {};
    float run_m[2][2], run_l[2][2];
    #pragma unroll
    for (int im = 0; im < 2; im++)
        #pragma unroll
        for (int rs = 0; rs < 2; rs++) { run_m[im][rs] = -1e30f; run_l[im][rs] = 0.f; }

    for (int ch = 0; ch < 4; ch++) {
        __syncthreads();   // previous chunk fully consumed
        // load K/V chunk (64 keys)
        for (int i = tid; i < 2 * 64 * 16; i += 256) {
            int part = i >> 10;                 // 0 = K, 1 = V
            int r = (i >> 4) & 63, c4 = (i & 15) * 4;
            int coff = (part ? 1152 : 1024) + g * HDd;
            float4 v = *(const float4*)(QKV +
                ((size_t)b*Ls + kbase + ch*64 + r)*QKVW + coff + c4);
            bf* hp = part ? Vhp : Khp;
            bf* lp = part ? Vlp : Klp;
            int o = r * AQS + c4;
            bf h0 = __float2bfloat16(v.x), h1 = __float2bfloat16(v.y);
            bf h2 = __float2bfloat16(v.z), h3 = __float2bfloat16(v.w);
            *(bf2*)&hp[o]   = __halves2bfloat162(h0, h1);
            *(bf2*)&hp[o+2] = __halves2bfloat162(h2, h3);
            *(bf2*)&lp[o]   = __halves2bfloat162(__float2bfloat16(v.x - __bfloat162float(h0)),
                                                 __float2bfloat16(v.y - __bfloat162float(h1)));
            *(bf2*)&lp[o+2] = __halves2bfloat162(__float2bfloat16(v.z - __bfloat162float(h2)),
                                                 __float2bfloat16(v.w - __bfloat162float(h3)));
        }
        __syncthreads();

        // S = Q K^T  (warp tile 32 x 64)
        float s[2][8][4] = {};
        #pragma unroll
        for (int kk = 0; kk < 4; kk++) {
            uint32_t aQh[2][4], aQl[2][4];
            int arow = wid * 32 + (lane & 15);
            int acol = kk * 16 + (lane >> 4) * 8;
            #pragma unroll
            for (int im = 0; im < 2; im++) {
                uint32_t ad = sQ + ((arow + im * 16) * AQS + acol) * 2;
                ldsm4(aQh[im], ad);
                ldsm4(aQl[im], ad + 36864);
            }
            uint32_t bKh[8][2], bKl[8][2];
            int mtx = lane >> 3;
            int brow_off = (mtx >> 1) * 8 + (lane & 7);
            int bcol = kk * 16 + (mtx & 1) * 8;
            #pragma unroll
            for (int jp = 0; jp < 4; jp++) {
                uint32_t bd = sK + ((jp * 16 + brow_off) * AQS + bcol) * 2;
                uint32_t t4[4];
                ldsm4(t4, bd);
                bKh[2*jp][0] = t4[0]; bKh[2*jp][1] = t4[1];
                bKh[2*jp+1][0] = t4[2]; bKh[2*jp+1][1] = t4[3];
                ldsm4(t4, bd + 9216);
                bKl[2*jp][0] = t4[0]; bKl[2*jp][1] = t4[1];
                bKl[2*jp+1][0] = t4[2]; bKl[2*jp+1][1] = t4[3];
            }
            #pragma unroll
            for (int im = 0; im < 2; im++)
                #pragma unroll
                for (int j = 0; j < 8; j++) {
                    mma16816(s[im][j], aQh[im], bKh[j]);
                    mma16816(s[im][j], aQh[im], bKl[j]);
                    mma16816(s[im][j], aQl[im], bKh[j]);
                }
        }

        // online softmax (scale 1/8)
        #pragma unroll
        for (int im = 0; im < 2; im++)
            #pragma unroll
            for (int j = 0; j < 8; j++)
                #pragma unroll
                for (int q = 0; q < 4; q++) s[im][j][q] *= 0.125f;

        #pragma unroll
        for (int im = 0; im < 2; im++) {
            #pragma unroll
            for (int rs = 0; rs < 2; rs++) {
                float mx = -1e30f;
                #pragma unroll
                for (int j = 0; j < 8; j++)
                    mx = fmaxf(mx, fmaxf(s[im][j][rs*2], s[im][j][rs*2+1]));
                mx = fmaxf(mx, __shfl_xor_sync(0xffffffffu, mx, 1));
                mx = fmaxf(mx, __shfl_xor_sync(0xffffffffu, mx, 2));
                float nm = fmaxf(run_m[im][rs], mx);
                float corr = __expf(run_m[im][rs] - nm);
                run_m[im][rs] = nm;
                float rsum = 0.f;
                #pragma unroll
                for (int j = 0; j < 8; j++) {
                    float p0 = __expf(s[im][j][rs*2]   - nm);
                    float p1 = __expf(s[im][j][rs*2+1] - nm);
                    s[im][j][rs*2] = p0; s[im][j][rs*2+1] = p1;
                    rsum += p0 + p1;
                }
                rsum += __shfl_xor_sync(0xffffffffu, rsum, 1);
                rsum += __shfl_xor_sync(0xffffffffu, rsum, 2);
                run_l[im][rs] = run_l[im][rs] * corr + rsum;
                #pragma unroll
                for (int j = 0; j < 8; j++) {
                    o_acc[im][j][rs*2]   *= corr;
                    o_acc[im][j][rs*2+1] *= corr;
                }
            }
        }

        // O += P V  (P from s fragments; V via ldmatrix.trans)
        #pragma unroll
        for (int t = 0; t < 4; t++) {
            uint32_t aPh[2][4], aPl[2][4];
            #pragma unroll
            for (int im = 0; im < 2; im++) {
                float p00 = s[im][2*t][0],   p01 = s[im][2*t][1];
                float p02 = s[im][2*t][2],   p03 = s[im][2*t][3];
                float p10 = s[im][2*t+1][0], p11 = s[im][2*t+1][1];
                float p12 = s[im][2*t+1][2], p13 = s[im][2*t+1][3];
                aPh[im][0] = packbf(p00, p01);
                aPh[im][1] = packbf(p02, p03);
                aPh[im][2] = packbf(p10, p11);
                aPh[im][3] = packbf(p12, p13);
                float l00 = p00 - __bfloat162float(__float2bfloat16(p00));
                float l01 = p01 - __bfloat162float(__float2bfloat16(p01));
                float l02 = p02 - __bfloat162float(__float2bfloat16(p02));
                float l03 = p03 - __bfloat162float(__float2bfloat16(p03));
                float l10 = p10 - __bfloat162float(__float2bfloat16(p10));
                float l11 = p11 - __bfloat162float(__float2bfloat16(p11));
                float l12 = p12 - __bfloat162float(__float2bfloat16(p12));
                float l13 = p13 - __bfloat162float(__float2bfloat16(p13));
                aPl[im][0] = packbf(l00, l01);
                aPl[im][1] = packbf(l02, l03);
                aPl[im][2] = packbf(l10, l11);
                aPl[im][3] = packbf(l12, l13);
            }
            uint32_t bVh[8][2], bVl[8][2];
            int mtx = lane >> 3;
            int krow = t * 16 + (mtx & 1) * 8 + (lane & 7);
            int ncol = (mtx >> 1) * 8;
            #pragma unroll
            for (int jp = 0; jp < 4; jp++) {
                uint32_t bd = sV + (krow * AQS + jp * 16 + ncol) * 2;
                uint32_t t4[4];
                ldsm4t(t4, bd);
                bVh[2*jp][0] = t4[0]; bVh[2*jp][1] = t4[1];
                bVh[2*jp+1][0] = t4[2]; bVh[2*jp+1][1] = t4[3];
                ldsm4t(t4, bd + 9216);
                bVl[2*jp][0] = t4[0]; bVl[2*jp][1] = t4[1];
                bVl[2*jp+1][0] = t4[2]; bVl[2*jp+1][1] = t4[3];
            }
            #pragma unroll
            for (int im = 0; im < 2; im++)
                #pragma unroll
                for (int j = 0; j < 8; j++) {
                    mma16816(o_acc[im][j], aPh[im], bVh[j]);
                    mma16816(o_acc[im][j], aPh[im], bVl[j]);
                    mma16816(o_acc[im][j], aPl[im], bVh[j]);
                }
        }
    }

    // epilogue: normalize + hi/lo write
    #pragma unroll
    for (int im = 0; im < 2; im++) {
        #pragma unroll
        for (int rs = 0; rs < 2; rs++) {
            float inv = 1.f / run_l[im][rs];
            int r = wid * 32 + im * 16 + (lane >> 2) + rs * 8;
            size_t ob = ((size_t)b * Ls + n * WINs + r) * Dd + h * HDd;
            #pragma unroll
            for (int j = 0; j < 8; j++) {
                int col = j * 8 + (lane & 3) * 2;
                float v0 = o_acc[im][j][rs*2] * inv;
                float v1 = o_acc[im][j][rs*2+1] * inv;
                bf h0 = __float2bfloat16(v0), h1 = __float2bfloat16(v1);
                *(bf2*)&Oh[ob + col] = __halves2bfloat162(h0, h1);
                *(bf2*)&Ol[ob + col] = __halves2bfloat162(
                    __float2bfloat16(v0 - __bfloat162float(h0)),
                    __float2bfloat16(v1 - __bfloat162float(h1)));
            }
        }
    }
}

// ---------------- gating ----------------------------------------------------
__global__ __launch_bounds__(256) void gate_kernel(
    const float* __restrict__ X, const float* __restrict__ Wg,
    const float* __restrict__ bg)
{
    int tok  = (blockIdx.x * 256 + threadIdx.x) >> 5;
    int lane = threadIdx.x & 31;
    if (tok >= NTOK) return;
    const float* xr = X + (size_t)tok * Dd;
    float a[Ee];
    #pragma unroll
    for (int e = 0; e < Ee; e++) a[e] = 0.f;
    for (int d = lane; d < Dd; d += 32) {
        float xv = xr[d];
        const float4* wr = (const float4*)&Wg[d * Ee];
        float4 w0 = wr[0], w1 = wr[1];
        a[0] += xv * w0.x; a[1] += xv * w0.y; a[2] += xv * w0.z; a[3] += xv * w0.w;
        a[4] += xv * w1.x; a[5] += xv * w1.y; a[6] += xv * w1.z; a[7] += xv * w1.w;
    }
    #pragma unroll
    for (int e = 0; e < Ee; e++)
        #pragma unroll
        for (int o = 16; o; o >>= 1) a[e] += __shfl_xor_sync(0xffffffffu, a[e], o);
    if (lane == 0) {
        float mx = -1e30f;
        #pragma unroll
        for (int e = 0; e < Ee; e++) { a[e] += bg[e]; mx = fmaxf(mx, a[e]); }
        float p[Ee], se = 0.f;
        #pragma unroll
        for (int e = 0; e < Ee; e++) { p[e] = __expf(a[e] - mx); se += p[e]; }
        float inv = 1.f / se, ent = 0.f;
        #pragma unroll
        for (int e = 0; e < Ee; e++) { p[e] *= inv; ent -= p[e] * logf(p[e] + 1e-8f); }
        atomicAdd(&g_entsum, ent);
        int i0 = 0;
        #pragma unroll
        for (int e = 1; e < Ee; e++) if (p[e] > p[i0]) i0 = e;
        int i1 = -1;
        #pragma unroll
        for (int e = 0; e < Ee; e++) {
            if (e == i0) continue;
            if (i1 < 0 || p[e] > p[i1]) i1 = e;
        }
        int p0 = atomicAdd(&g_cnt[i0], 1);
        g_list[i0][p0] = tok * 2;     g_wl2[i0][p0] = p[i0];
        int p1 = atomicAdd(&g_cnt[i1], 1);
        g_list[i1][p1] = tok * 2 + 1; g_wl2[i1][p1] = p[i1];
    }
}

// ---------------- fuse + aux ------------------------------------------------
__global__ __launch_bounds__(256) void fuse_kernel(float* __restrict__ out) {
    size_t i = (size_t)blockIdx.x * 256 + threadIdx.x;
    float4 a = ((const float4*)g_part)[i];
    float4 b = ((const float4*)(g_part + (size_t)NTOK * HIDs))[i];
    float4 o = ((float4*)out)[i];
    o.x += a.x + b.x; o.y += a.y + b.y; o.z += a.z + b.z; o.w += a.w + b.w;
    ((float4*)out)[i] = o;
}

__global__ void fin_kernel(float* __restrict__ out) {
    float pen = 0.f;
    #pragma unroll
    for (int e = 0; e < Ee; e++) {
        float usage = (float)g_cnt[e] / (8192.f + 1e-8f);
        pen += fmaxf(usage - 0.4f, 0.f);
    }
    out[(size_t)NTOK * Dd] = 0.05f * (g_entsum / (float)NTOK) + pen;
}

// ---------------- launch ----------------------------------------------------
extern "C" void kernel_launch(void* const* d_in, const int* in_sizes, int n_in,
                              void* d_out, int out_size)
{
    (void)in_sizes; (void)n_in;
    const float* x    = (const float*)d_in[0];
    const float* Wq   = (const float*)d_in[1];
    const float* bq   = (const float*)d_in[2];
    const float* Wk   = (const float*)d_in[3];
    const float* bk   = (const float*)d_in[4];
    const float* Wv   = (const float*)d_in[5];
    const float* bv   = (const float*)d_in[6];
    const float* Wo   = (const float*)d_in[7];
    const float* bo   = (const float*)d_in[8];
    const float* ln1g = (const float*)d_in[9];
    const float* ln1b = (const float*)d_in[10];
    const float* ln2g = (const float*)d_in[11];
    const float* ln2b = (const float*)d_in[12];
    const float* Wg   = (const float*)d_in[13];
    const float* bg   = (const float*)d_in[14];
    const float* We   = (const float*)d_in[15];
    const float* be   = (const float*)d_in[16];
    float* out = (float*)d_out;

    float *p_qkv, *p_ln2, *p_bqkv;
    bf *p_ah, *p_al, *p_oh, *p_ol, *p_2h, *p_2l;
    bf *p_wh, *p_wl, *p_woh, *p_wol, *p_weh, *p_wel;
    cudaGetSymbolAddress((void**)&p_qkv, g_qkv);
    cudaGetSymbolAddress((void**)&p_ln2, g_ln2);
    cudaGetSymbolAddress((void**)&p_bqkv, g_bqkv);
    cudaGetSymbolAddress((void**)&p_ah,  g_ah);
    cudaGetSymbolAddress((void**)&p_al,  g_al);
    cudaGetSymbolAddress((void**)&p_oh,  g_oh);
    cudaGetSymbolAddress((void**)&p_ol,  g_ol);
    cudaGetSymbolAddress((void**)&p_2h,  g_2h);
    cudaGetSymbolAddress((void**)&p_2l,  g_2l);
    cudaGetSymbolAddress((void**)&p_wh,  g_wh);
    cudaGetSymbolAddress((void**)&p_wl,  g_wl);
    cudaGetSymbolAddress((void**)&p_woh, g_woh);
    cudaGetSymbolAddress((void**)&p_wol, g_wol);
    cudaGetSymbolAddress((void**)&p_weh, g_weh);
    cudaGetSymbolAddress((void**)&p_wel, g_wel);

    const int GSMEM = 4 * STAGEB;  // 160 KB
    cudaFuncSetAttribute(gemm_mma, cudaFuncAttributeMaxDynamicSharedMemorySize, GSMEM);
    const int ASMEM = 110592;      // attn smem
    cudaFuncSetAttribute(attn_mma, cudaFuncAttributeMaxDynamicSharedMemorySize, ASMEM);

    // launch order tuned so ncu (-s 5 -c 1) captures gemm_mma (QKV)
    init_kernel<<<1, 32>>>();                                   // 0
    catb_a<<<4, 256>>>(bq);                                     // 1
    catb_b<<<1, 256>>>(bk, bv);                                 // 2
    ln_kernel<<<NTOK, 256>>>(x, ln1g, ln1b, nullptr, p_ah, p_al); // 3
    tconv_all<<<dim3(32, 32, 12), 256>>>(Wq, Wk, Wv, Wo, We);   // 4
    gemm_mma<<<dim3(10, 17, 2), 256, GSMEM>>>(p_ah, p_al, p_wh, p_wl, p_bqkv,
                                              nullptr, p_qkv, Ls, QKVW, 0); // 5 (profiled)
    attn_mma<<<dim3(16, Hh, 2), 256, ASMEM>>>(p_qkv, p_oh, p_ol);
    gemm_mma<<<dim3(8, 64, 1), 256, GSMEM>>>(p_oh, p_ol, p_woh, p_wol, bo,
                                             x, out, 0, Dd, 0);
    ln_kernel<<<NTOK, 256>>>(out, ln2g, ln2b, p_ln2, p_2h, p_2l);
    gate_kernel<<<NTOK * 32 / 256, 256>>>(p_ln2, Wg, bg);
    gemm_mma<<<dim3(8, 64, 8), 256, GSMEM>>>(p_2h, p_2l, p_weh, p_wel, be,
                                             nullptr, nullptr, 0, HIDs, 1);
    fuse_kernel<<<NTOK * HIDs / 1024, 256>>>(out);
    if (out_size > NTOK * Dd) fin_kernel<<<1, 1>>>(out);
}

// round 11
// speedup vs baseline: 1.6970x; 1.6970x over previous
#include <cuda_runtime.h>
#include <cuda_fp16.h>
#include <math.h>
#include <stdint.h>

#define Dd   1024
#define Ls   4096
#define NTOK 8192
#define HDd  64
#define WINs 256
#define Gg   2
#define Hh   16
#define Ee   8
#define HIDs 1024
#define QKVW 1280      // 1024 q + 128 k + 128 v
#define STRD 40        // padded fp16 row stride in gemm smem tiles
#define STAGEB 20480   // bytes per gemm pipeline stage (A 10240 + B 10240)
#define NSTG 6

typedef __half hf;
typedef __half2 hf2;

// ---------------- device scratch --------------------------------------------
__device__ float g_qkv[NTOK * QKVW];            // fused q|k|v fp32
__device__ hf    g_a[NTOK * Dd];                // ln1 fp16
__device__ hf    g_o[NTOK * Dd];                // attn out fp16
__device__ float g_ln2[NTOK * Dd];
__device__ hf    g_2[NTOK * Dd];                // ln2 fp16
__device__ hf    g_w[QKVW * Dd];                // [Wq;Wk;Wv]^T fp16
__device__ hf    g_wo[Dd * Dd];
__device__ hf    g_we[Ee * HIDs * Dd];
__device__ float g_bqkv[QKVW];
__device__ float g_part[2 * NTOK * HIDs];
__device__ int   g_cnt[Ee];
__device__ int   g_list[Ee][NTOK];
__device__ float g_wl2[Ee][NTOK];
__device__ float g_entsum;

// ---------------- helpers ---------------------------------------------------
__device__ __forceinline__ uint32_t s2u(const void* p) {
    uint32_t a;
    asm("{ .reg .u64 t; cvta.to.shared.u64 t, %1; cvt.u32.u64 %0, t; }"
        : "=r"(a) : "l"(p));
    return a;
}
__device__ __forceinline__ void ldsm4(uint32_t* r, uint32_t addr) {
    asm volatile("ldmatrix.sync.aligned.m8n8.x4.shared.b16 {%0,%1,%2,%3}, [%4];"
                 : "=r"(r[0]), "=r"(r[1]), "=r"(r[2]), "=r"(r[3]) : "r"(addr));
}
__device__ __forceinline__ void mma16816(float* c, const uint32_t* a, const uint32_t* b) {
    asm volatile(
        "mma.sync.aligned.m16n8k16.row.col.f32.f16.f16.f32 "
        "{%0,%1,%2,%3}, {%4,%5,%6,%7}, {%8,%9}, {%0,%1,%2,%3};"
        : "+f"(c[0]), "+f"(c[1]), "+f"(c[2]), "+f"(c[3])
        : "r"(a[0]), "r"(a[1]), "r"(a[2]), "r"(a[3]), "r"(b[0]), "r"(b[1]));
}
__device__ __forceinline__ void cpa16(uint32_t dst, const void* src) {
    asm volatile("cp.async.cg.shared.global [%0], [%1], 16;" :: "r"(dst), "l"(src));
}

// ---------------- init / bias concat ----------------------------------------
__global__ void init_kernel() {
    int t = threadIdx.x;
    if (t < Ee) g_cnt[t] = 0;
    if (t == 0) g_entsum = 0.f;
}
__global__ void catb_a(const float* bq) {
    int i = blockIdx.x * 256 + threadIdx.x;
    g_bqkv[i] = bq[i];
}
__global__ void catb_b(const float* bk, const float* bv) {
    int t = threadIdx.x;
    if (t < 128) g_bqkv[1024 + t] = bk[t];
    else g_bqkv[1024 + t] = bv[t - 128];
}

// ---------------- layernorm with fp16 emit -----------------------------------
__device__ __forceinline__ float brsum(float v, float* sh) {
    int lane = threadIdx.x & 31, w = threadIdx.x >> 5;
    #pragma unroll
    for (int o = 16; o; o >>= 1) v += __shfl_xor_sync(0xffffffffu, v, o);
    if (lane == 0) sh[w] = v;
    __syncthreads();
    if (w == 0) {
        float r = (lane < 8) ? sh[lane] : 0.f;
        #pragma unroll
        for (int o = 4; o; o >>= 1) r += __shfl_xor_sync(0xffffffffu, r, o);
        if (lane == 0) sh[0] = r;
    }
    __syncthreads();
    float r = sh[0];
    __syncthreads();
    return r;
}

__global__ __launch_bounds__(256) void ln_kernel(
    const float* __restrict__ x, const float* __restrict__ g,
    const float* __restrict__ b, float* __restrict__ outf,
    hf* __restrict__ oh)
{
    __shared__ float sh[8];
    size_t row = blockIdx.x;
    int tid = threadIdx.x;
    float4 v = ((const float4*)(x + row * Dd))[tid];
    float mean = brsum(v.x + v.y + v.z + v.w, sh) * (1.f / Dd);
    float d0 = v.x - mean, d1 = v.y - mean, d2 = v.z - mean, d3 = v.w - mean;
    float var = brsum(d0*d0 + d1*d1 + d2*d2 + d3*d3, sh) * (1.f / Dd);
    float inv = rsqrtf(var + 1e-5f);
    float4 gv = ((const float4*)g)[tid];
    float4 bv = ((const float4*)b)[tid];
    float o0 = d0*inv*gv.x + bv.x, o1 = d1*inv*gv.y + bv.y;
    float o2 = d2*inv*gv.z + bv.z, o3 = d3*inv*gv.w + bv.w;
    if (outf) ((float4*)(outf + row * Dd))[tid] = make_float4(o0, o1, o2, o3);
    hf2* hp = (hf2*)(oh + row * Dd);
    hp[2*tid]   = __floats2half2_rn(o0, o1);
    hp[2*tid+1] = __floats2half2_rn(o2, o3);
}

// ---------------- merged weight transpose + fp16 convert ---------------------
// z=0: Wq  z=1: Wk  z=2: Wv  z=3: Wo  z=4..11: We[e]
__global__ __launch_bounds__(256) void tconv_all(
    const float* __restrict__ Wq, const float* __restrict__ Wk,
    const float* __restrict__ Wv, const float* __restrict__ Wo,
    const float* __restrict__ We)
{
    __shared__ float t[32][33];
    int z = blockIdx.z;
    const float* W; hf* Th; int Nc;
    if (z == 0)      { W = Wq; Th = g_w; Nc = 1024; }
    else if (z == 1) { W = Wk; Th = g_w + (size_t)1024 * Dd; Nc = 128; }
    else if (z == 2) { W = Wv; Th = g_w + (size_t)1152 * Dd; Nc = 128; }
    else if (z == 3) { W = Wo; Th = g_wo; Nc = 1024; }
    else {
        int e = z - 4;
        W = We + (size_t)e * Dd * HIDs;
        Th = g_we + (size_t)e * Dd * HIDs;
        Nc = 1024;
    }
    int n0 = blockIdx.x * 32;
    if (n0 >= Nc) return;
    int k0 = blockIdx.y * 32;
    int tx = threadIdx.x & 31, ty = threadIdx.x >> 5;
    #pragma unroll
    for (int r = 0; r < 4; r++)
        t[ty + 8*r][tx] = W[(size_t)(k0 + ty + 8*r) * Nc + n0 + tx];
    __syncthreads();
    #pragma unroll
    for (int r = 0; r < 4; r++)
        Th[(size_t)(n0 + ty + 8*r) * Dd + k0 + tx] = __float2half(t[tx][ty + 8*r]);
}

// ---------------- fp16 HMMA GEMM, 6-stage cp.async pipeline -------------------
// C[m,n] = sum_k A[m,k]*Wt[n,k] + bias[n] (+res). K = 1024 always.
// mode 0: row0 = z*zRow + y*128, fp32 C (ldc). mode 1: MoE gather/scatter.
__global__ __launch_bounds__(256, 1) void gemm_mma(
    const hf* __restrict__ Ah, const hf* __restrict__ Bh,
    const float* __restrict__ bias, const float* __restrict__ res,
    float* __restrict__ C, int zRow, int ldc, int mode)
{
    extern __shared__ hf sm[];
    __shared__ int s_ent[128];
    __shared__ float s_w[128];
    __shared__ int s_ridx[128];

    int tid = threadIdx.x, lane = tid & 31, wid = tid >> 5;
    int n0 = blockIdx.x * 128;
    int row0 = 0, cnt = 0, m0 = 0;
    const hf* bmat = Bh;
    const float* bptr = bias;
    if (mode == 1) {
        int e = blockIdx.z;
        cnt = g_cnt[e];
        m0 = blockIdx.y * 128;
        if (m0 >= cnt) return;
        bmat = Bh + ((size_t)e << 20);
        bptr = bias + e * HIDs;
        if (tid < 128) {
            int m = m0 + tid;
            int ent = (m < cnt) ? g_list[e][m] : -1;
            s_ent[tid] = ent;
            s_ridx[tid] = (ent >= 0) ? (ent >> 1) : -1;
            s_w[tid] = (m < cnt) ? g_wl2[e][m] : 0.f;
        }
        __syncthreads();
    } else {
        row0 = blockIdx.z * zRow + blockIdx.y * 128;
    }
    const int* rp = (mode == 1) ? s_ridx : nullptr;
    uint32_t sb = s2u(sm);

    float c[4][4][4] = {};
    int wm = (wid & 1) * 64, wn = (wid >> 1) * 32;

    #define LOAD_STAGE(s, k0)                                                   \
    do {                                                                        \
        for (int i = tid; i < 1024; i += 256) {                                 \
            int part = i >> 9, r = (i >> 2) & 127, cb = (i & 3) * 8;            \
            uint32_t dst = sb + (s) * STAGEB + part * 10240 + (r * STRD + cb) * 2;\
            if (part == 0) {                                                    \
                int grow = rp ? rp[r] : (row0 + r);                             \
                if (grow < 0) continue;                                         \
                cpa16(dst, Ah + ((size_t)grow << 10) + (k0) + cb);              \
            } else {                                                            \
                cpa16(dst, bmat + ((size_t)(n0 + r) << 10) + (k0) + cb);        \
            }                                                                   \
        }                                                                       \
        asm volatile("cp.async.commit_group;");                                 \
    } while (0)

    LOAD_STAGE(0, 0);
    LOAD_STAGE(1, 32);
    LOAD_STAGE(2, 64);
    LOAD_STAGE(3, 96);
    LOAD_STAGE(4, 128);

    for (int cc = 0; cc < 32; cc++) {
        asm volatile("cp.async.wait_group 4;");   // stage cc complete
        __syncthreads();
        if (cc < 27) {
            int st = (cc + 5) % NSTG;             // FIX: proper ring modulo
            LOAD_STAGE(st, (cc + 5) * 32);
        } else {
            asm volatile("cp.async.commit_group;");
        }

        uint32_t base = sb + (cc % NSTG) * STAGEB;
        #pragma unroll
        for (int ka = 0; ka < 2; ka++) {
            uint32_t a[4][4], b[4][2];
            int arow = wm + (lane & 15);
            int acol = ka * 16 + (lane >> 4) * 8;
            #pragma unroll
            for (int im = 0; im < 4; im++)
                ldsm4(a[im], base + ((arow + im * 16) * STRD + acol) * 2);
            int mtx = lane >> 3;
            int brow_off = (mtx >> 1) * 8 + (lane & 7);
            int bcol = ka * 16 + (mtx & 1) * 8;
            #pragma unroll
            for (int inb = 0; inb < 4; inb += 2) {
                uint32_t t4[4];
                ldsm4(t4, base + 10240 + ((wn + inb * 8 + brow_off) * STRD + bcol) * 2);
                b[inb][0] = t4[0];   b[inb][1] = t4[1];
                b[inb+1][0] = t4[2]; b[inb+1][1] = t4[3];
            }
            #pragma unroll
            for (int im = 0; im < 4; im++)
                #pragma unroll
                for (int in = 0; in < 4; in++)
                    mma16816(c[im][in], a[im], b[in]);
        }
        __syncthreads();
    }

    int crow = lane >> 2, ccol = (lane & 3) * 2;
    #pragma unroll
    for (int im = 0; im < 4; im++) {
        #pragma unroll
        for (int h2 = 0; h2 < 2; h2++) {
            int r = wm + im * 16 + crow + h2 * 8;
            if (mode == 0) {
                size_t m = (size_t)(row0 + r);
                #pragma unroll
                for (int in = 0; in < 4; in++) {
                    int n = n0 + wn + in * 8 + ccol;
                    float2 v;
                    v.x = c[im][in][h2*2+0] + bptr[n];
                    v.y = c[im][in][h2*2+1] + bptr[n+1];
                    if (res) {
                        float2 q = *(const float2*)&res[m * ldc + n];
                        v.x += q.x; v.y += q.y;
                    }
                    *(float2*)&C[m * ldc + n] = v;
                }
            } else if (m0 + r < cnt) {
                int ent = s_ent[r];
                int tok = ent >> 1, slot = ent & 1;
                float w = s_w[r];
                float* dst = g_part + (((size_t)slot * NTOK + tok) << 10);
                #pragma unroll
                for (int in = 0; in < 4; in++) {
                    int n = n0 + wn + in * 8 + ccol;
                    float2 v;
                    v.x = w * (c[im][in][h2*2+0] + bptr[n]);
                    v.y = w * (c[im][in][h2*2+1] + bptr[n+1]);
                    *(float2*)&dst[n] = v;
                }
            }
        }
    }
}

// ---------------- scalar windowed GQA attention (fused QKV, fp16 out) -------
__global__ __launch_bounds__(256, 1) void attn_kernel(
    const float* __restrict__ QKV, hf* __restrict__ Oh)
{
    extern __shared__ float smem[];
    float* Ks = smem;
    float* Vs = smem + WINs * HDd;
    int n = blockIdx.x, h = blockIdx.y, b = blockIdx.z;
    int g = h & (Gg - 1);
    int kbase = n * (WINs / 2);
    const float* Kg = QKV + ((size_t)b * Ls + kbase) * QKVW + 1024 + g * HDd;
    const float* Vg = QKV + ((size_t)b * Ls + kbase) * QKVW + 1152 + g * HDd;
    for (int i = threadIdx.x; i < WINs * HDd / 4; i += 256) {
        int r = i >> 4, c = (i & 15) * 4;
        *(float4*)&Ks[r * HDd + c] = *(const float4*)&Kg[(size_t)r * QKVW + c];
        *(float4*)&Vs[r * HDd + c] = *(const float4*)&Vg[(size_t)r * QKVW + c];
    }
    __syncthreads();
    int w = threadIdx.x;
    const float* qr = QKV + ((size_t)b * Ls + kbase + w) * QKVW + h * HDd;
    float q[HDd], acc[HDd];
    #pragma unroll
    for (int i = 0; i < HDd; i++) { q[i] = qr[i] * 0.125f; acc[i] = 0.f; }
    float mrun = -1e30f, lrun = 0.f;
    for (int kc = 0; kc < WINs; kc += 8) {
        float s[8];
        #pragma unroll
        for (int j = 0; j < 8; j++) {
            const float* kr = &Ks[(kc + j) * HDd];
            float d = 0.f;
            #pragma unroll
            for (int i = 0; i < HDd; i++) d += q[i] * kr[i];
            s[j] = d;
        }
        float cm = s[0];
        #pragma unroll
        for (int j = 1; j < 8; j++) cm = fmaxf(cm, s[j]);
        float nm = fmaxf(mrun, cm);
        float sc = __expf(mrun - nm);
        lrun *= sc;
        #pragma unroll
        for (int i = 0; i < HDd; i++) acc[i] *= sc;
        #pragma unroll
        for (int j = 0; j < 8; j++) {
            float ev = __expf(s[j] - nm);
            lrun += ev;
            const float* vr = &Vs[(kc + j) * HDd];
            #pragma unroll
            for (int i = 0; i < HDd; i++) acc[i] += ev * vr[i];
        }
        mrun = nm;
    }
    float inv = 1.f / lrun;
    size_t ob = ((size_t)b * Ls + n * WINs + w) * Dd + h * HDd;
    #pragma unroll
    for (int i = 0; i < HDd; i += 2)
        *(hf2*)&Oh[ob + i] = __floats2half2_rn(acc[i] * inv, acc[i+1] * inv);
}

// ---------------- gating ----------------------------------------------------
__global__ __launch_bounds__(256) void gate_kernel(
    const float* __restrict__ X, const float* __restrict__ Wg,
    const float* __restrict__ bg)
{
    int tok  = (blockIdx.x * 256 + threadIdx.x) >> 5;
    int lane = threadIdx.x & 31;
    if (tok >= NTOK) return;
    const float* xr = X + (size_t)tok * Dd;
    float a[Ee];
    #pragma unroll
    for (int e = 0; e < Ee; e++) a[e] = 0.f;
    for (int d = lane; d < Dd; d += 32) {
        float xv = xr[d];
        const float4* wr = (const float4*)&Wg[d * Ee];
        float4 w0 = wr[0], w1 = wr[1];
        a[0] += xv * w0.x; a[1] += xv * w0.y; a[2] += xv * w0.z; a[3] += xv * w0.w;
        a[4] += xv * w1.x; a[5] += xv * w1.y; a[6] += xv * w1.z; a[7] += xv * w1.w;
    }
    #pragma unroll
    for (int e = 0; e < Ee; e++)
        #pragma unroll
        for (int o = 16; o; o >>= 1) a[e] += __shfl_xor_sync(0xffffffffu, a[e], o);
    if (lane == 0) {
        float mx = -1e30f;
        #pragma unroll
        for (int e = 0; e < Ee; e++) { a[e] += bg[e]; mx = fmaxf(mx, a[e]); }
        float p[Ee], se = 0.f;
        #pragma unroll
        for (int e = 0; e < Ee; e++) { p[e] = __expf(a[e] - mx); se += p[e]; }
        float inv = 1.f / se, ent = 0.f;
        #pragma unroll
        for (int e = 0; e < Ee; e++) { p[e] *= inv; ent -= p[e] * logf(p[e] + 1e-8f); }
        atomicAdd(&g_entsum, ent);
        int i0 = 0;
        #pragma unroll
        for (int e = 1; e < Ee; e++) if (p[e] > p[i0]) i0 = e;
        int i1 = -1;
        #pragma unroll
        for (int e = 0; e < Ee; e++) {
            if (e == i0) continue;
            if (i1 < 0 || p[e] > p[i1]) i1 = e;
        }
        int p0 = atomicAdd(&g_cnt[i0], 1);
        g_list[i0][p0] = tok * 2;     g_wl2[i0][p0] = p[i0];
        int p1 = atomicAdd(&g_cnt[i1], 1);
        g_list[i1][p1] = tok * 2 + 1; g_wl2[i1][p1] = p[i1];
    }
}

// ---------------- fuse + aux ------------------------------------------------
__global__ __launch_bounds__(256) void fuse_kernel(float* __restrict__ out) {
    size_t i = (size_t)blockIdx.x * 256 + threadIdx.x;
    float4 a = ((const float4*)g_part)[i];
    float4 b = ((const float4*)(g_part + (size_t)NTOK * HIDs))[i];
    float4 o = ((float4*)out)[i];
    o.x += a.x + b.x; o.y += a.y + b.y; o.z += a.z + b.z; o.w += a.w + b.w;
    ((float4*)out)[i] = o;
}

__global__ void fin_kernel(float* __restrict__ out) {
    float pen = 0.f;
    #pragma unroll
    for (int e = 0; e < Ee; e++) {
        float usage = (float)g_cnt[e] / (8192.f + 1e-8f);
        pen += fmaxf(usage - 0.4f, 0.f);
    }
    out[(size_t)NTOK * Dd] = 0.05f * (g_entsum / (float)NTOK) + pen;
}

// ---------------- launch ----------------------------------------------------
extern "C" void kernel_launch(void* const* d_in, const int* in_sizes, int n_in,
                              void* d_out, int out_size)
{
    (void)in_sizes; (void)n_in;
    const float* x    = (const float*)d_in[0];
    const float* Wq   = (const float*)d_in[1];
    const float* bq   = (const float*)d_in[2];
    const float* Wk   = (const float*)d_in[3];
    const float* bk   = (const float*)d_in[4];
    const float* Wv   = (const float*)d_in[5];
    const float* bv   = (const float*)d_in[6];
    const float* Wo   = (const float*)d_in[7];
    const float* bo   = (const float*)d_in[8];
    const float* ln1g = (const float*)d_in[9];
    const float* ln1b = (const float*)d_in[10];
    const float* ln2g = (const float*)d_in[11];
    const float* ln2b = (const float*)d_in[12];
    const float* Wg   = (const float*)d_in[13];
    const float* bg   = (const float*)d_in[14];
    const float* We   = (const float*)d_in[15];
    const float* be   = (const float*)d_in[16];
    float* out = (float*)d_out;

    float *p_qkv, *p_ln2, *p_bqkv;
    hf *p_a, *p_o, *p_2, *p_w, *p_wo, *p_we;
    cudaGetSymbolAddress((void**)&p_qkv, g_qkv);
    cudaGetSymbolAddress((void**)&p_ln2, g_ln2);
    cudaGetSymbolAddress((void**)&p_bqkv, g_bqkv);
    cudaGetSymbolAddress((void**)&p_a,  g_a);
    cudaGetSymbolAddress((void**)&p_o,  g_o);
    cudaGetSymbolAddress((void**)&p_2,  g_2);
    cudaGetSymbolAddress((void**)&p_w,  g_w);
    cudaGetSymbolAddress((void**)&p_wo, g_wo);
    cudaGetSymbolAddress((void**)&p_we, g_we);

    const int GSMEM = NSTG * STAGEB;  // 120 KB
    cudaFuncSetAttribute(gemm_mma, cudaFuncAttributeMaxDynamicSharedMemorySize, GSMEM);
    const int ASMEM = 2 * WINs * HDd * sizeof(float);  // 128 KB
    cudaFuncSetAttribute(attn_kernel, cudaFuncAttributeMaxDynamicSharedMemorySize, ASMEM);

    init_kernel<<<1, 32>>>();
    catb_a<<<4, 256>>>(bq);
    catb_b<<<1, 256>>>(bk, bv);
    ln_kernel<<<NTOK, 256>>>(x, ln1g, ln1b, nullptr, p_a);
    tconv_all<<<dim3(32, 32, 12), 256>>>(Wq, Wk, Wv, Wo, We);

    // fused QKV: rows < 2176 per batch (17 M-tiles), N = 1280 (10 tiles)
    gemm_mma<<<dim3(10, 17, 2), 256, GSMEM>>>(p_a, p_w, p_bqkv,
                                              nullptr, p_qkv, Ls, QKVW, 0);

    attn_kernel<<<dim3(16, Hh, 2), 256, ASMEM>>>(p_qkv, p_o);

    // h = x + O @ Wo + bo -> d_out
    gemm_mma<<<dim3(8, 64, 1), 256, GSMEM>>>(p_o, p_wo, bo, x, out, 0, Dd, 0);

    ln_kernel<<<NTOK, 256>>>(out, ln2g, ln2b, p_ln2, p_2);
    gate_kernel<<<NTOK * 32 / 256, 256>>>(p_ln2, Wg, bg);
    gemm_mma<<<dim3(8, 64, 8), 256, GSMEM>>>(p_2, p_we, be,
                                             nullptr, nullptr, 0, HIDs, 1);
    fuse_kernel<<<NTOK * HIDs / 1024, 256>>>(out);
    if (out_size > NTOK * Dd) fin_kernel<<<1, 1>>>(out);
}

// round 13
// speedup vs baseline: 2.6882x; 1.5841x over previous
#include <cuda_runtime.h>
#include <cuda_fp16.h>
#include <math.h>
#include <stdint.h>

#define Dd   1024
#define Ls   4096
#define NTOK 8192
#define HDd  64
#define WINs 256
#define Gg   2
#define Hh   16
#define Ee   8
#define HIDs 1024
#define QKVW 1280      // 1024 q + 128 k + 128 v
#define STRD 40        // padded fp16 row stride in gemm smem tiles
#define STAGEB 20480   // bytes per gemm pipeline stage
#define NSTG 6
#define AQS  72        // attn smem row stride (hf elems)

typedef __half hf;
typedef __half2 hf2;

// ---------------- device scratch --------------------------------------------
__device__ hf    g_qkvh[NTOK * QKVW];           // fused q|k|v fp16
__device__ hf    g_a[NTOK * Dd];                // ln1 fp16
__device__ hf    g_o[NTOK * Dd];                // attn out fp16
__device__ float g_ln2[NTOK * Dd];
__device__ hf    g_2[NTOK * Dd];                // ln2 fp16
__device__ hf    g_w[QKVW * Dd];                // [Wq;Wk;Wv]^T fp16
__device__ hf    g_wo[Dd * Dd];
__device__ hf    g_we[Ee * HIDs * Dd];
__device__ float g_bqkv[QKVW];
__device__ float g_part[2 * NTOK * HIDs];
__device__ int   g_cnt[Ee];
__device__ int   g_list[Ee][NTOK];
__device__ float g_wl2[Ee][NTOK];
__device__ float g_entsum;

// ---------------- helpers ---------------------------------------------------
__device__ __forceinline__ uint32_t s2u(const void* p) {
    uint32_t a;
    asm("{ .reg .u64 t; cvta.to.shared.u64 t, %1; cvt.u32.u64 %0, t; }"
        : "=r"(a) : "l"(p));
    return a;
}
__device__ __forceinline__ void ldsm4(uint32_t* r, uint32_t addr) {
    asm volatile("ldmatrix.sync.aligned.m8n8.x4.shared.b16 {%0,%1,%2,%3}, [%4];"
                 : "=r"(r[0]), "=r"(r[1]), "=r"(r[2]), "=r"(r[3]) : "r"(addr));
}
__device__ __forceinline__ void ldsm4t(uint32_t* r, uint32_t addr) {
    asm volatile("ldmatrix.sync.aligned.m8n8.x4.trans.shared.b16 {%0,%1,%2,%3}, [%4];"
                 : "=r"(r[0]), "=r"(r[1]), "=r"(r[2]), "=r"(r[3]) : "r"(addr));
}
__device__ __forceinline__ void mma16816(float* c, const uint32_t* a, const uint32_t* b) {
    asm volatile(
        "mma.sync.aligned.m16n8k16.row.col.f32.f16.f16.f32 "
        "{%0,%1,%2,%3}, {%4,%5,%6,%7}, {%8,%9}, {%0,%1,%2,%3};"
        : "+f"(c[0]), "+f"(c[1]), "+f"(c[2]), "+f"(c[3])
        : "r"(a[0]), "r"(a[1]), "r"(a[2]), "r"(a[3]), "r"(b[0]), "r"(b[1]));
}
__device__ __forceinline__ void cpa16(uint32_t dst, const void* src) {
    asm volatile("cp.async.cg.shared.global [%0], [%1], 16;" :: "r"(dst), "l"(src));
}
__device__ __forceinline__ uint32_t packhf(float a, float b) {
    hf2 t = __floats2half2_rn(a, b);
    return *(uint32_t*)&t;
}

// ---------------- init / bias concat ----------------------------------------
__global__ void init_kernel() {
    int t = threadIdx.x;
    if (t < Ee) g_cnt[t] = 0;
    if (t == 0) g_entsum = 0.f;
}
__global__ void catb_a(const float* bq) {
    int i = blockIdx.x * 256 + threadIdx.x;
    g_bqkv[i] = bq[i];
}
__global__ void catb_b(const float* bk, const float* bv) {
    int t = threadIdx.x;
    if (t < 128) g_bqkv[1024 + t] = bk[t];
    else g_bqkv[1024 + t] = bv[t - 128];
}

// ---------------- layernorm with fp16 emit -----------------------------------
__device__ __forceinline__ float brsum(float v, float* sh) {
    int lane = threadIdx.x & 31, w = threadIdx.x >> 5;
    #pragma unroll
    for (int o = 16; o; o >>= 1) v += __shfl_xor_sync(0xffffffffu, v, o);
    if (lane == 0) sh[w] = v;
    __syncthreads();
    if (w == 0) {
        float r = (lane < 8) ? sh[lane] : 0.f;
        #pragma unroll
        for (int o = 4; o; o >>= 1) r += __shfl_xor_sync(0xffffffffu, r, o);
        if (lane == 0) sh[0] = r;
    }
    __syncthreads();
    float r = sh[0];
    __syncthreads();
    return r;
}

__global__ __launch_bounds__(256) void ln_kernel(
    const float* __restrict__ x, const float* __restrict__ g,
    const float* __restrict__ b, float* __restrict__ outf,
    hf* __restrict__ oh)
{
    __shared__ float sh[8];
    size_t row = blockIdx.x;
    int tid = threadIdx.x;
    float4 v = ((const float4*)(x + row * Dd))[tid];
    float mean = brsum(v.x + v.y + v.z + v.w, sh) * (1.f / Dd);
    float d0 = v.x - mean, d1 = v.y - mean, d2 = v.z - mean, d3 = v.w - mean;
    float var = brsum(d0*d0 + d1*d1 + d2*d2 + d3*d3, sh) * (1.f / Dd);
    float inv = rsqrtf(var + 1e-5f);
    float4 gv = ((const float4*)g)[tid];
    float4 bv = ((const float4*)b)[tid];
    float o0 = d0*inv*gv.x + bv.x, o1 = d1*inv*gv.y + bv.y;
    float o2 = d2*inv*gv.z + bv.z, o3 = d3*inv*gv.w + bv.w;
    if (outf) ((float4*)(outf + row * Dd))[tid] = make_float4(o0, o1, o2, o3);
    hf2* hp = (hf2*)(oh + row * Dd);
    hp[2*tid]   = __floats2half2_rn(o0, o1);
    hp[2*tid+1] = __floats2half2_rn(o2, o3);
}

// ---------------- merged weight transpose + fp16 convert ---------------------
__global__ __launch_bounds__(256) void tconv_all(
    const float* __restrict__ Wq, const float* __restrict__ Wk,
    const float* __restrict__ Wv, const float* __restrict__ Wo,
    const float* __restrict__ We)
{
    __shared__ float t[32][33];
    int z = blockIdx.z;
    const float* W; hf* Th; int Nc;
    if (z == 0)      { W = Wq; Th = g_w; Nc = 1024; }
    else if (z == 1) { W = Wk; Th = g_w + (size_t)1024 * Dd; Nc = 128; }
    else if (z == 2) { W = Wv; Th = g_w + (size_t)1152 * Dd; Nc = 128; }
    else if (z == 3) { W = Wo; Th = g_wo; Nc = 1024; }
    else {
        int e = z - 4;
        W = We + (size_t)e * Dd * HIDs;
        Th = g_we + (size_t)e * Dd * HIDs;
        Nc = 1024;
    }
    int n0 = blockIdx.x * 32;
    if (n0 >= Nc) return;
    int k0 = blockIdx.y * 32;
    int tx = threadIdx.x & 31, ty = threadIdx.x >> 5;
    #pragma unroll
    for (int r = 0; r < 4; r++)
        t[ty + 8*r][tx] = W[(size_t)(k0 + ty + 8*r) * Nc + n0 + tx];
    __syncthreads();
    #pragma unroll
    for (int r = 0; r < 4; r++)
        Th[(size_t)(n0 + ty + 8*r) * Dd + k0 + tx] = __float2half(t[tx][ty + 8*r]);
}

// ---------------- fp16 HMMA GEMM, 6-stage cp.async pipeline -------------------
// mode 0: fp32 C. mode 1: MoE gather/scatter. mode 2: fp16 Ch output.
__global__ __launch_bounds__(256, 1) void gemm_mma(
    const hf* __restrict__ Ah, const hf* __restrict__ Bh,
    const float* __restrict__ bias, const float* __restrict__ res,
    float* __restrict__ C, hf* __restrict__ Ch, int zRow, int ldc, int mode)
{
    extern __shared__ hf sm[];
    __shared__ int s_ent[128];
    __shared__ float s_w[128];
    __shared__ int s_ridx[128];

    int tid = threadIdx.x, lane = tid & 31, wid = tid >> 5;
    int n0 = blockIdx.x * 128;
    int row0 = 0, cnt = 0, m0 = 0;
    const hf* bmat = Bh;
    const float* bptr = bias;
    if (mode == 1) {
        int e = blockIdx.z;
        cnt = g_cnt[e];
        m0 = blockIdx.y * 128;
        if (m0 >= cnt) return;
        bmat = Bh + ((size_t)e << 20);
        bptr = bias + e * HIDs;
        if (tid < 128) {
            int m = m0 + tid;
            int ent = (m < cnt) ? g_list[e][m] : -1;
            s_ent[tid] = ent;
            s_ridx[tid] = (ent >= 0) ? (ent >> 1) : -1;
            s_w[tid] = (m < cnt) ? g_wl2[e][m] : 0.f;
        }
        __syncthreads();
    } else {
        row0 = blockIdx.z * zRow + blockIdx.y * 128;
    }
    const int* rp = (mode == 1) ? s_ridx : nullptr;
    uint32_t sb = s2u(sm);

    float c[4][4][4] = {};
    int wm = (wid & 1) * 64, wn = (wid >> 1) * 32;

    #define LOAD_STAGE(s, k0)                                                   \
    do {                                                                        \
        for (int i = tid; i < 1024; i += 256) {                                 \
            int part = i >> 9, r = (i >> 2) & 127, cb = (i & 3) * 8;            \
            uint32_t dst = sb + (s) * STAGEB + part * 10240 + (r * STRD + cb) * 2;\
            if (part == 0) {                                                    \
                int grow = rp ? rp[r] : (row0 + r);                             \
                if (grow < 0) continue;                                         \
                cpa16(dst, Ah + ((size_t)grow << 10) + (k0) + cb);              \
            } else {                                                            \
                cpa16(dst, bmat + ((size_t)(n0 + r) << 10) + (k0) + cb);        \
            }                                                                   \
        }                                                                       \
        asm volatile("cp.async.commit_group;");                                 \
    } while (0)

    LOAD_STAGE(0, 0);
    LOAD_STAGE(1, 32);
    LOAD_STAGE(2, 64);
    LOAD_STAGE(3, 96);
    LOAD_STAGE(4, 128);

    for (int cc = 0; cc < 32; cc++) {
        asm volatile("cp.async.wait_group 4;");
        __syncthreads();
        if (cc < 27) {
            int st = (cc + 5) % NSTG;
            LOAD_STAGE(st, (cc + 5) * 32);
        } else {
            asm volatile("cp.async.commit_group;");
        }

        uint32_t base = sb + (cc % NSTG) * STAGEB;
        #pragma unroll
        for (int ka = 0; ka < 2; ka++) {
            uint32_t a[4][4], b[4][2];
            int arow = wm + (lane & 15);
            int acol = ka * 16 + (lane >> 4) * 8;
            #pragma unroll
            for (int im = 0; im < 4; im++)
                ldsm4(a[im], base + ((arow + im * 16) * STRD + acol) * 2);
            int mtx = lane >> 3;
            int brow_off = (mtx >> 1) * 8 + (lane & 7);
            int bcol = ka * 16 + (mtx & 1) * 8;
            #pragma unroll
            for (int inb = 0; inb < 4; inb += 2) {
                uint32_t t4[4];
                ldsm4(t4, base + 10240 + ((wn + inb * 8 + brow_off) * STRD + bcol) * 2);
                b[inb][0] = t4[0];   b[inb][1] = t4[1];
                b[inb+1][0] = t4[2]; b[inb+1][1] = t4[3];
            }
            #pragma unroll
            for (int im = 0; im < 4; im++)
                #pragma unroll
                for (int in = 0; in < 4; in++)
                    mma16816(c[im][in], a[im], b[in]);
        }
        __syncthreads();
    }

    int crow = lane >> 2, ccol = (lane & 3) * 2;
    #pragma unroll
    for (int im = 0; im < 4; im++) {
        #pragma unroll
        for (int h2 = 0; h2 < 2; h2++) {
            int r = wm + im * 16 + crow + h2 * 8;
            if (mode == 0) {
                size_t m = (size_t)(row0 + r);
                #pragma unroll
                for (int in = 0; in < 4; in++) {
                    int n = n0 + wn + in * 8 + ccol;
                    float2 v;
                    v.x = c[im][in][h2*2+0] + bptr[n];
                    v.y = c[im][in][h2*2+1] + bptr[n+1];
                    if (res) {
                        float2 q = *(const float2*)&res[m * ldc + n];
                        v.x += q.x; v.y += q.y;
                    }
                    *(float2*)&C[m * ldc + n] = v;
                }
            } else if (mode == 2) {
                size_t m = (size_t)(row0 + r);
                #pragma unroll
                for (int in = 0; in < 4; in++) {
                    int n = n0 + wn + in * 8 + ccol;
                    *(hf2*)&Ch[m * ldc + n] = __floats2half2_rn(
                        c[im][in][h2*2+0] + bptr[n],
                        c[im][in][h2*2+1] + bptr[n+1]);
                }
            } else if (m0 + r < cnt) {
                int ent = s_ent[r];
                int tok = ent >> 1, slot = ent & 1;
                float w = s_w[r];
                float* dst = g_part + (((size_t)slot * NTOK + tok) << 10);
                #pragma unroll
                for (int in = 0; in < 4; in++) {
                    int n = n0 + wn + in * 8 + ccol;
                    float2 v;
                    v.x = w * (c[im][in][h2*2+0] + bptr[n]);
                    v.y = w * (c[im][in][h2*2+1] + bptr[n+1]);
                    *(float2*)&dst[n] = v;
                }
            }
        }
    }
}

// ---------------- fp16 HMMA flash attention ---------------------------------
// block = (window n, head h, batch b); 8 warps; warp owns 32 q-rows.
// Q 256x64 resident fp16, K/V streamed in 4 chunks of 64 keys via cp.async.
__global__ __launch_bounds__(256, 1) void attn_mma(
    const hf* __restrict__ QKV, hf* __restrict__ Oh)
{
    extern __shared__ hf smn[];
    uint32_t sQ = s2u(smn);              // 256*72*2 = 36864 B
    uint32_t sK = sQ + 36864;            // 64*72*2 = 9216 B
    uint32_t sV = sK + 9216;             // 9216 B; total 55296 B

    int n = blockIdx.x, h = blockIdx.y, b = blockIdx.z;
    int g = h & (Gg - 1);
    int kbase = n * (WINs / 2);
    int tid = threadIdx.x, lane = tid & 31, wid = tid >> 5;

    // Q load: 256 rows x 64 hf = 8 x 16B per row
    for (int i = tid; i < 2048; i += 256) {
        int r = i >> 3, cb = (i & 7) * 8;
        cpa16(sQ + (r * AQS + cb) * 2,
              QKV + ((size_t)(b * Ls + kbase + r)) * QKVW + h * HDd + cb);
    }
    asm volatile("cp.async.commit_group;");

    float o_acc[2][8][4] = {};
    float run_m[2][2], run_l[2][2];
    #pragma unroll
    for (int im = 0; im < 2; im++)
        #pragma unroll
        for (int rs = 0; rs < 2; rs++) { run_m[im][rs] = -1e30f; run_l[im][rs] = 0.f; }

    for (int ch = 0; ch < 4; ch++) {
        if (ch > 0) __syncthreads();   // prior chunk fully consumed
        for (int i = tid; i < 1024; i += 256) {
            int part = i >> 9;          // 0 = K, 1 = V
            int r = (i >> 3) & 63, cb = (i & 7) * 8;
            int coff = (part ? 1152 : 1024) + g * HDd;
            cpa16((part ? sV : sK) + (r * AQS + cb) * 2,
                  QKV + ((size_t)(b * Ls + kbase + ch * 64 + r)) * QKVW + coff + cb);
        }
        asm volatile("cp.async.commit_group;");
        asm volatile("cp.async.wait_group 0;");
        __syncthreads();

        // S = Q K^T  (warp tile 32 x 64)
        float s[2][8][4] = {};
        #pragma unroll
        for (int kk = 0; kk < 4; kk++) {
            uint32_t aQ[2][4], bK[8][2];
            int arow = wid * 32 + (lane & 15);
            int acol = kk * 16 + (lane >> 4) * 8;
            #pragma unroll
            for (int im = 0; im < 2; im++)
                ldsm4(aQ[im], sQ + ((arow + im * 16) * AQS + acol) * 2);
            int mtx = lane >> 3;
            int brow_off = (mtx >> 1) * 8 + (lane & 7);
            int bcol = kk * 16 + (mtx & 1) * 8;
            #pragma unroll
            for (int jp = 0; jp < 4; jp++) {
                uint32_t t4[4];
                ldsm4(t4, sK + ((jp * 16 + brow_off) * AQS + bcol) * 2);
                bK[2*jp][0] = t4[0];   bK[2*jp][1] = t4[1];
                bK[2*jp+1][0] = t4[2]; bK[2*jp+1][1] = t4[3];
            }
            #pragma unroll
            for (int im = 0; im < 2; im++)
                #pragma unroll
                for (int j = 0; j < 8; j++)
                    mma16816(s[im][j], aQ[im], bK[j]);
        }

        // online softmax (scale 1/8); quad lanes share rows
        #pragma unroll
        for (int im = 0; im < 2; im++) {
            #pragma unroll
            for (int rs = 0; rs < 2; rs++) {
                float mx = -1e30f;
                #pragma unroll
                for (int j = 0; j < 8; j++)
                    mx = fmaxf(mx, fmaxf(s[im][j][rs*2], s[im][j][rs*2+1]));
                mx = fmaxf(mx, __shfl_xor_sync(0xffffffffu, mx, 1));
                mx = fmaxf(mx, __shfl_xor_sync(0xffffffffu, mx, 2));
                mx *= 0.125f;
                float nm = fmaxf(run_m[im][rs], mx);
                float corr = __expf(run_m[im][rs] - nm);
                run_m[im][rs] = nm;
                float rsum = 0.f;
                #pragma unroll
                for (int j = 0; j < 8; j++) {
                    float p0 = __expf(s[im][j][rs*2]   * 0.125f - nm);
                    float p1 = __expf(s[im][j][rs*2+1] * 0.125f - nm);
                    s[im][j][rs*2] = p0; s[im][j][rs*2+1] = p1;
                    rsum += p0 + p1;
                }
                rsum += __shfl_xor_sync(0xffffffffu, rsum, 1);
                rsum += __shfl_xor_sync(0xffffffffu, rsum, 2);
                run_l[im][rs] = run_l[im][rs] * corr + rsum;
                #pragma unroll
                for (int j = 0; j < 8; j++) {
                    o_acc[im][j][rs*2]   *= corr;
                    o_acc[im][j][rs*2+1] *= corr;
                }
            }
        }

        // O += P V  (P from s fragments — C->A layout identity; V via ldsm.trans)
        #pragma unroll
        for (int t = 0; t < 4; t++) {
            uint32_t aP[2][4];
            #pragma unroll
            for (int im = 0; im < 2; im++) {
                aP[im][0] = packhf(s[im][2*t][0],   s[im][2*t][1]);
                aP[im][1] = packhf(s[im][2*t][2],   s[im][2*t][3]);
                aP[im][2] = packhf(s[im][2*t+1][0], s[im][2*t+1][1]);
                aP[im][3] = packhf(s[im][2*t+1][2], s[im][2*t+1][3]);
            }
            uint32_t bV[8][2];
            int mtx = lane >> 3;
            int krow = t * 16 + (mtx & 1) * 8 + (lane & 7);
            int ncol = (mtx >> 1) * 8;
            #pragma unroll
            for (int jp = 0; jp < 4; jp++) {
                uint32_t t4[4];
                ldsm4t(t4, sV + (krow * AQS + jp * 16 + ncol) * 2);
                bV[2*jp][0] = t4[0];   bV[2*jp][1] = t4[1];
                bV[2*jp+1][0] = t4[2]; bV[2*jp+1][1] = t4[3];
            }
            #pragma unroll
            for (int im = 0; im < 2; im++)
                #pragma unroll
                for (int j = 0; j < 8; j++)
                    mma16816(o_acc[im][j], aP[im], bV[j]);
        }
    }

    // epilogue: normalize + fp16 write
    #pragma unroll
    for (int im = 0; im < 2; im++) {
        #pragma unroll
        for (int rs = 0; rs < 2; rs++) {
            float inv = 1.f / run_l[im][rs];
            int r = wid * 32 + im * 16 + (lane >> 2) + rs * 8;
            size_t ob = ((size_t)b * Ls + n * WINs + r) * Dd + h * HDd;
            #pragma unroll
            for (int j = 0; j < 8; j++) {
                int col = j * 8 + (lane & 3) * 2;
                *(hf2*)&Oh[ob + col] = __floats2half2_rn(
                    o_acc[im][j][rs*2] * inv, o_acc[im][j][rs*2+1] * inv);
            }
        }
    }
}

// ---------------- gating ----------------------------------------------------
__global__ __launch_bounds__(256) void gate_kernel(
    const float* __restrict__ X, const float* __restrict__ Wg,
    const float* __restrict__ bg)
{
    int tok  = (blockIdx.x * 256 + threadIdx.x) >> 5;
    int lane = threadIdx.x & 31;
    if (tok >= NTOK) return;
    const float* xr = X + (size_t)tok * Dd;
    float a[Ee];
    #pragma unroll
    for (int e = 0; e < Ee; e++) a[e] = 0.f;
    for (int d = lane; d < Dd; d += 32) {
        float xv = xr[d];
        const float4* wr = (const float4*)&Wg[d * Ee];
        float4 w0 = wr[0], w1 = wr[1];
        a[0] += xv * w0.x; a[1] += xv * w0.y; a[2] += xv * w0.z; a[3] += xv * w0.w;
        a[4] += xv * w1.x; a[5] += xv * w1.y; a[6] += xv * w1.z; a[7] += xv * w1.w;
    }
    #pragma unroll
    for (int e = 0; e < Ee; e++)
        #pragma unroll
        for (int o = 16; o; o >>= 1) a[e] += __shfl_xor_sync(0xffffffffu, a[e], o);
    if (lane == 0) {
        float mx = -1e30f;
        #pragma unroll
        for (int e = 0; e < Ee; e++) { a[e] += bg[e]; mx = fmaxf(mx, a[e]); }
        float p[Ee], se = 0.f;
        #pragma unroll
        for (int e = 0; e < Ee; e++) { p[e] = __expf(a[e] - mx); se += p[e]; }
        float inv = 1.f / se, ent = 0.f;
        #pragma unroll
        for (int e = 0; e < Ee; e++) { p[e] *= inv; ent -= p[e] * logf(p[e] + 1e-8f); }
        atomicAdd(&g_entsum, ent);
        int i0 = 0;
        #pragma unroll
        for (int e = 1; e < Ee; e++) if (p[e] > p[i0]) i0 = e;
        int i1 = -1;
        #pragma unroll
        for (int e = 0; e < Ee; e++) {
            if (e == i0) continue;
            if (i1 < 0 || p[e] > p[i1]) i1 = e;
        }
        int p0 = atomicAdd(&g_cnt[i0], 1);
        g_list[i0][p0] = tok * 2;     g_wl2[i0][p0] = p[i0];
        int p1 = atomicAdd(&g_cnt[i1], 1);
        g_list[i1][p1] = tok * 2 + 1; g_wl2[i1][p1] = p[i1];
    }
}

// ---------------- fuse + aux ------------------------------------------------
__global__ __launch_bounds__(256) void fuse_kernel(float* __restrict__ out) {
    size_t i = (size_t)blockIdx.x * 256 + threadIdx.x;
    float4 a = ((const float4*)g_part)[i];
    float4 b = ((const float4*)(g_part + (size_t)NTOK * HIDs))[i];
    float4 o = ((float4*)out)[i];
    o.x += a.x + b.x; o.y += a.y + b.y; o.z += a.z + b.z; o.w += a.w + b.w;
    ((float4*)out)[i] = o;
}

__global__ void fin_kernel(float* __restrict__ out) {
    float pen = 0.f;
    #pragma unroll
    for (int e = 0; e < Ee; e++) {
        float usage = (float)g_cnt[e] / (8192.f + 1e-8f);
        pen += fmaxf(usage - 0.4f, 0.f);
    }
    out[(size_t)NTOK * Dd] = 0.05f * (g_entsum / (float)NTOK) + pen;
}

// ---------------- launch ----------------------------------------------------
extern "C" void kernel_launch(void* const* d_in, const int* in_sizes, int n_in,
                              void* d_out, int out_size)
{
    (void)in_sizes; (void)n_in;
    const float* x    = (const float*)d_in[0];
    const float* Wq   = (const float*)d_in[1];
    const float* bq   = (const float*)d_in[2];
    const float* Wk   = (const float*)d_in[3];
    const float* bk   = (const float*)d_in[4];
    const float* Wv   = (const float*)d_in[5];
    const float* bv   = (const float*)d_in[6];
    const float* Wo   = (const float*)d_in[7];
    const float* bo   = (const float*)d_in[8];
    const float* ln1g = (const float*)d_in[9];
    const float* ln1b = (const float*)d_in[10];
    const float* ln2g = (const float*)d_in[11];
    const float* ln2b = (const float*)d_in[12];
    const float* Wg   = (const float*)d_in[13];
    const float* bg   = (const float*)d_in[14];
    const float* We   = (const float*)d_in[15];
    const float* be   = (const float*)d_in[16];
    float* out = (float*)d_out;

    float *p_ln2, *p_bqkv;
    hf *p_qkvh, *p_a, *p_o, *p_2, *p_w, *p_wo, *p_we;
    cudaGetSymbolAddress((void**)&p_qkvh, g_qkvh);
    cudaGetSymbolAddress((void**)&p_ln2, g_ln2);
    cudaGetSymbolAddress((void**)&p_bqkv, g_bqkv);
    cudaGetSymbolAddress((void**)&p_a,  g_a);
    cudaGetSymbolAddress((void**)&p_o,  g_o);
    cudaGetSymbolAddress((void**)&p_2,  g_2);
    cudaGetSymbolAddress((void**)&p_w,  g_w);
    cudaGetSymbolAddress((void**)&p_wo, g_wo);
    cudaGetSymbolAddress((void**)&p_we, g_we);

    const int GSMEM = NSTG * STAGEB;  // 120 KB
    cudaFuncSetAttribute(gemm_mma, cudaFuncAttributeMaxDynamicSharedMemorySize, GSMEM);
    const int ASMEM = 55296;          // 54 KB
    cudaFuncSetAttribute(attn_mma, cudaFuncAttributeMaxDynamicSharedMemorySize, ASMEM);

    init_kernel<<<1, 32>>>();
    catb_a<<<4, 256>>>(bq);
    catb_b<<<1, 256>>>(bk, bv);
    ln_kernel<<<NTOK, 256>>>(x, ln1g, ln1b, nullptr, p_a);
    tconv_all<<<dim3(32, 32, 12), 256>>>(Wq, Wk, Wv, Wo, We);

    // fused QKV (fp16 out): rows < 2176 per batch, N = 1280
    gemm_mma<<<dim3(10, 17, 2), 256, GSMEM>>>(p_a, p_w, p_bqkv, nullptr,
                                              nullptr, p_qkvh, Ls, QKVW, 2);

    attn_mma<<<dim3(16, Hh, 2), 256, ASMEM>>>(p_qkvh, p_o);

    // h = x + O @ Wo + bo -> d_out
    gemm_mma<<<dim3(8, 64, 1), 256, GSMEM>>>(p_o, p_wo, bo, x, out, nullptr,
                                             0, Dd, 0);

    ln_kernel<<<NTOK, 256>>>(out, ln2g, ln2b, p_ln2, p_2);
    gate_kernel<<<NTOK * 32 / 256, 256>>>(p_ln2, Wg, bg);
    gemm_mma<<<dim3(8, 64, 8), 256, GSMEM>>>(p_2, p_we, be, nullptr,
                                             nullptr, nullptr, 0, HIDs, 1);
    fuse_kernel<<<NTOK * HIDs / 1024, 256>>>(out);
    if (out_size > NTOK * Dd) fin_kernel<<<1, 1>>>(out);
}

// round 14
// speedup vs baseline: 3.4342x; 1.2775x over previous
#include <cuda_runtime.h>
#include <cuda_fp16.h>
#include <math.h>
#include <stdint.h>

#define Dd   1024
#define Ls   4096
#define NTOK 8192
#define HDd  64
#define WINs 256
#define Gg   2
#define Hh   16
#define Ee   8
#define HIDs 1024
#define QKVW 1280      // 1024 q + 128 k + 128 v
#define SRD  72        // padded fp16 row stride (BK=64 + 8)
#define STAGEB 36864   // bytes per gemm stage: 2 x 128 x 72 x 2
#define NSTG 3
#define AQS  72        // attn smem row stride (hf elems)

typedef __half hf;
typedef __half2 hf2;

// ---------------- device scratch --------------------------------------------
__device__ hf    g_qkvh[NTOK * QKVW];           // fused q|k|v fp16
__device__ hf    g_a[NTOK * Dd];                // ln1 fp16
__device__ hf    g_o[NTOK * Dd];                // attn out fp16
__device__ hf    g_2[NTOK * Dd];                // ln2 fp16
__device__ hf    g_w[QKVW * Dd];                // [Wq;Wk;Wv]^T fp16
__device__ hf    g_wo[Dd * Dd];
__device__ hf    g_we[Ee * HIDs * Dd];
__device__ float g_bqkv[QKVW];
__device__ int   g_cnt[Ee];
__device__ int   g_list[Ee][NTOK];
__device__ float g_wl2[Ee][NTOK];
__device__ float g_entsum;

// ---------------- helpers ---------------------------------------------------
__device__ __forceinline__ uint32_t s2u(const void* p) {
    uint32_t a;
    asm("{ .reg .u64 t; cvta.to.shared.u64 t, %1; cvt.u32.u64 %0, t; }"
        : "=r"(a) : "l"(p));
    return a;
}
__device__ __forceinline__ void ldsm4(uint32_t* r, uint32_t addr) {
    asm volatile("ldmatrix.sync.aligned.m8n8.x4.shared.b16 {%0,%1,%2,%3}, [%4];"
                 : "=r"(r[0]), "=r"(r[1]), "=r"(r[2]), "=r"(r[3]) : "r"(addr));
}
__device__ __forceinline__ void ldsm4t(uint32_t* r, uint32_t addr) {
    asm volatile("ldmatrix.sync.aligned.m8n8.x4.trans.shared.b16 {%0,%1,%2,%3}, [%4];"
                 : "=r"(r[0]), "=r"(r[1]), "=r"(r[2]), "=r"(r[3]) : "r"(addr));
}
__device__ __forceinline__ void mma16816(float* c, const uint32_t* a, const uint32_t* b) {
    asm volatile(
        "mma.sync.aligned.m16n8k16.row.col.f32.f16.f16.f32 "
        "{%0,%1,%2,%3}, {%4,%5,%6,%7}, {%8,%9}, {%0,%1,%2,%3};"
        : "+f"(c[0]), "+f"(c[1]), "+f"(c[2]), "+f"(c[3])
        : "r"(a[0]), "r"(a[1]), "r"(a[2]), "r"(a[3]), "r"(b[0]), "r"(b[1]));
}
__device__ __forceinline__ void cpa16(uint32_t dst, const void* src) {
    asm volatile("cp.async.cg.shared.global [%0], [%1], 16;" :: "r"(dst), "l"(src));
}
__device__ __forceinline__ uint32_t packhf(float a, float b) {
    hf2 t = __floats2half2_rn(a, b);
    return *(uint32_t*)&t;
}

// ---------------- init / bias concat ----------------------------------------
__global__ void init_kernel() {
    int t = threadIdx.x;
    if (t < Ee) g_cnt[t] = 0;
    if (t == 0) g_entsum = 0.f;
}
__global__ void catb_a(const float* bq) {
    int i = blockIdx.x * 256 + threadIdx.x;
    g_bqkv[i] = bq[i];
}
__global__ void catb_b(const float* bk, const float* bv) {
    int t = threadIdx.x;
    if (t < 128) g_bqkv[1024 + t] = bk[t];
    else g_bqkv[1024 + t] = bv[t - 128];
}

// ---------------- layernorm (+ optional fused MoE gate) ----------------------
__device__ __forceinline__ float brsum(float v, float* sh) {
    int lane = threadIdx.x & 31, w = threadIdx.x >> 5;
    #pragma unroll
    for (int o = 16; o; o >>= 1) v += __shfl_xor_sync(0xffffffffu, v, o);
    if (lane == 0) sh[w] = v;
    __syncthreads();
    if (w == 0) {
        float r = (lane < 8) ? sh[lane] : 0.f;
        #pragma unroll
        for (int o = 4; o; o >>= 1) r += __shfl_xor_sync(0xffffffffu, r, o);
        if (lane == 0) sh[0] = r;
    }
    __syncthreads();
    float r = sh[0];
    __syncthreads();
    return r;
}

__global__ __launch_bounds__(256) void ln_kernel(
    const float* __restrict__ x, const float* __restrict__ g,
    const float* __restrict__ b, hf* __restrict__ oh,
    const float* __restrict__ Wg, const float* __restrict__ bg)
{
    __shared__ float sh[8];
    __shared__ float shg[8][8];
    size_t row = blockIdx.x;
    int tid = threadIdx.x, lane = tid & 31, wid = tid >> 5;
    float4 v = ((const float4*)(x + row * Dd))[tid];
    float mean = brsum(v.x + v.y + v.z + v.w, sh) * (1.f / Dd);
    float d0 = v.x - mean, d1 = v.y - mean, d2 = v.z - mean, d3 = v.w - mean;
    float var = brsum(d0*d0 + d1*d1 + d2*d2 + d3*d3, sh) * (1.f / Dd);
    float inv = rsqrtf(var + 1e-5f);
    float4 gv = ((const float4*)g)[tid];
    float4 bv = ((const float4*)b)[tid];
    float o0 = d0*inv*gv.x + bv.x, o1 = d1*inv*gv.y + bv.y;
    float o2 = d2*inv*gv.z + bv.z, o3 = d3*inv*gv.w + bv.w;
    hf2* hp = (hf2*)(oh + row * Dd);
    hp[2*tid]   = __floats2half2_rn(o0, o1);
    hp[2*tid+1] = __floats2half2_rn(o2, o3);

    if (Wg) {
        float acc[8] = {};
        float ov[4] = {o0, o1, o2, o3};
        const float4* wr = (const float4*)&Wg[(size_t)(4*tid) * Ee];
        #pragma unroll
        for (int r = 0; r < 4; r++) {
            float4 wa = wr[2*r], wb = wr[2*r+1];
            acc[0] += ov[r]*wa.x; acc[1] += ov[r]*wa.y;
            acc[2] += ov[r]*wa.z; acc[3] += ov[r]*wa.w;
            acc[4] += ov[r]*wb.x; acc[5] += ov[r]*wb.y;
            acc[6] += ov[r]*wb.z; acc[7] += ov[r]*wb.w;
        }
        #pragma unroll
        for (int e = 0; e < Ee; e++)
            #pragma unroll
            for (int o = 16; o; o >>= 1)
                acc[e] += __shfl_xor_sync(0xffffffffu, acc[e], o);
        if (lane == 0)
            #pragma unroll
            for (int e = 0; e < Ee; e++) shg[wid][e] = acc[e];
        __syncthreads();
        if (tid == 0) {
            float p[Ee];
            float mx = -1e30f;
            #pragma unroll
            for (int e = 0; e < Ee; e++) {
                float l = bg[e];
                #pragma unroll
                for (int w = 0; w < 8; w++) l += shg[w][e];
                p[e] = l;
                mx = fmaxf(mx, l);
            }
            float se = 0.f;
            #pragma unroll
            for (int e = 0; e < Ee; e++) { p[e] = __expf(p[e] - mx); se += p[e]; }
            float invs = 1.f / se, ent = 0.f;
            #pragma unroll
            for (int e = 0; e < Ee; e++) { p[e] *= invs; ent -= p[e] * logf(p[e] + 1e-8f); }
            atomicAdd(&g_entsum, ent);
            int i0 = 0;
            #pragma unroll
            for (int e = 1; e < Ee; e++) if (p[e] > p[i0]) i0 = e;
            int i1 = -1;
            #pragma unroll
            for (int e = 0; e < Ee; e++) {
                if (e == i0) continue;
                if (i1 < 0 || p[e] > p[i1]) i1 = e;
            }
            int tok = (int)row;
            int p0 = atomicAdd(&g_cnt[i0], 1);
            g_list[i0][p0] = tok; g_wl2[i0][p0] = p[i0];
            int p1 = atomicAdd(&g_cnt[i1], 1);
            g_list[i1][p1] = tok; g_wl2[i1][p1] = p[i1];
        }
    }
}

// ---------------- merged weight transpose + fp16 convert ---------------------
__global__ __launch_bounds__(256) void tconv_all(
    const float* __restrict__ Wq, const float* __restrict__ Wk,
    const float* __restrict__ Wv, const float* __restrict__ Wo,
    const float* __restrict__ We)
{
    __shared__ float t[32][33];
    int z = blockIdx.z;
    const float* W; hf* Th; int Nc;
    if (z == 0)      { W = Wq; Th = g_w; Nc = 1024; }
    else if (z == 1) { W = Wk; Th = g_w + (size_t)1024 * Dd; Nc = 128; }
    else if (z == 2) { W = Wv; Th = g_w + (size_t)1152 * Dd; Nc = 128; }
    else if (z == 3) { W = Wo; Th = g_wo; Nc = 1024; }
    else {
        int e = z - 4;
        W = We + (size_t)e * Dd * HIDs;
        Th = g_we + (size_t)e * Dd * HIDs;
        Nc = 1024;
    }
    int n0 = blockIdx.x * 32;
    if (n0 >= Nc) return;
    int k0 = blockIdx.y * 32;
    int tx = threadIdx.x & 31, ty = threadIdx.x >> 5;
    #pragma unroll
    for (int r = 0; r < 4; r++)
        t[ty + 8*r][tx] = W[(size_t)(k0 + ty + 8*r) * Nc + n0 + tx];
    __syncthreads();
    #pragma unroll
    for (int r = 0; r < 4; r++)
        Th[(size_t)(n0 + ty + 8*r) * Dd + k0 + tx] = __float2half(t[tx][ty + 8*r]);
}

// ---------------- fp16 HMMA GEMM, BK=64, 3-stage pipeline, 2 CTA/SM ----------
// mode 0: fp32 C (+res). mode 1: MoE gather + atomic scatter into C.
// mode 2: fp16 Ch output.
__global__ __launch_bounds__(256, 2) void gemm_mma(
    const hf* __restrict__ Ah, const hf* __restrict__ Bh,
    const float* __restrict__ bias, const float* __restrict__ res,
    float* __restrict__ C, hf* __restrict__ Ch, int zRow, int ldc, int mode)
{
    extern __shared__ hf sm[];
    __shared__ int s_tok[128];
    __shared__ float s_w[128];

    int tid = threadIdx.x, lane = tid & 31, wid = tid >> 5;
    int n0 = blockIdx.x * 128;
    int row0 = 0, cnt = 0, m0 = 0;
    const hf* bmat = Bh;
    const float* bptr = bias;
    if (mode == 1) {
        int e = blockIdx.z;
        cnt = g_cnt[e];
        m0 = blockIdx.y * 128;
        if (m0 >= cnt) return;
        bmat = Bh + ((size_t)e << 20);
        bptr = bias + e * HIDs;
        if (tid < 128) {
            int m = m0 + tid;
            s_tok[tid] = (m < cnt) ? g_list[e][m] : -1;
            s_w[tid]   = (m < cnt) ? g_wl2[e][m] : 0.f;
        }
        __syncthreads();
    } else {
        row0 = blockIdx.z * zRow + blockIdx.y * 128;
    }
    const int* rp = (mode == 1) ? s_tok : nullptr;
    uint32_t sb = s2u(sm);

    float c[4][4][4] = {};
    int wm = (wid & 1) * 64, wn = (wid >> 1) * 32;

    #define LOAD_STAGE(s, k0)                                                   \
    do {                                                                        \
        for (int i = tid; i < 2048; i += 256) {                                 \
            int part = i >> 10, r = (i >> 3) & 127, cb = (i & 7) * 8;           \
            uint32_t dst = sb + (s) * STAGEB + part * 18432 + (r * SRD + cb) * 2;\
            if (part == 0) {                                                    \
                int grow = rp ? rp[r] : (row0 + r);                             \
                if (grow < 0) continue;                                         \
                cpa16(dst, Ah + ((size_t)grow << 10) + (k0) + cb);              \
            } else {                                                            \
                cpa16(dst, bmat + ((size_t)(n0 + r) << 10) + (k0) + cb);        \
            }                                                                   \
        }                                                                       \
        asm volatile("cp.async.commit_group;");                                 \
    } while (0)

    LOAD_STAGE(0, 0);
    LOAD_STAGE(1, 64);

    for (int cc = 0; cc < 16; cc++) {
        if (cc < 14) LOAD_STAGE((cc + 2) % NSTG, (cc + 2) * 64);
        else         asm volatile("cp.async.commit_group;");
        asm volatile("cp.async.wait_group 2;");   // stage cc complete
        __syncthreads();

        uint32_t base = sb + (cc % NSTG) * STAGEB;
        #pragma unroll
        for (int ka = 0; ka < 4; ka++) {
            uint32_t a[4][4], b[4][2];
            int arow = wm + (lane & 15);
            int acol = ka * 16 + (lane >> 4) * 8;
            #pragma unroll
            for (int im = 0; im < 4; im++)
                ldsm4(a[im], base + ((arow + im * 16) * SRD + acol) * 2);
            int mtx = lane >> 3;
            int brow_off = (mtx >> 1) * 8 + (lane & 7);
            int bcol = ka * 16 + (mtx & 1) * 8;
            #pragma unroll
            for (int inb = 0; inb < 4; inb += 2) {
                uint32_t t4[4];
                ldsm4(t4, base + 18432 + ((wn + inb * 8 + brow_off) * SRD + bcol) * 2);
                b[inb][0] = t4[0];   b[inb][1] = t4[1];
                b[inb+1][0] = t4[2]; b[inb+1][1] = t4[3];
            }
            #pragma unroll
            for (int im = 0; im < 4; im++)
                #pragma unroll
                for (int in = 0; in < 4; in++)
                    mma16816(c[im][in], a[im], b[in]);
        }
        __syncthreads();
    }

    int crow = lane >> 2, ccol = (lane & 3) * 2;
    #pragma unroll
    for (int im = 0; im < 4; im++) {
        #pragma unroll
        for (int h2 = 0; h2 < 2; h2++) {
            int r = wm + im * 16 + crow + h2 * 8;
            if (mode == 0) {
                size_t m = (size_t)(row0 + r);
                #pragma unroll
                for (int in = 0; in < 4; in++) {
                    int n = n0 + wn + in * 8 + ccol;
                    float2 v;
                    v.x = c[im][in][h2*2+0] + bptr[n];
                    v.y = c[im][in][h2*2+1] + bptr[n+1];
                    if (res) {
                        float2 q = *(const float2*)&res[m * ldc + n];
                        v.x += q.x; v.y += q.y;
                    }
                    *(float2*)&C[m * ldc + n] = v;
                }
            } else if (mode == 2) {
                size_t m = (size_t)(row0 + r);
                #pragma unroll
                for (int in = 0; in < 4; in++) {
                    int n = n0 + wn + in * 8 + ccol;
                    *(hf2*)&Ch[m * ldc + n] = __floats2half2_rn(
                        c[im][in][h2*2+0] + bptr[n],
                        c[im][in][h2*2+1] + bptr[n+1]);
                }
            } else if (m0 + r < cnt) {
                int tok = s_tok[r];
                float w = s_w[r];
                float* dst = C + ((size_t)tok << 10);
                #pragma unroll
                for (int in = 0; in < 4; in++) {
                    int n = n0 + wn + in * 8 + ccol;
                    atomicAdd(&dst[n],   w * (c[im][in][h2*2+0] + bptr[n]));
                    atomicAdd(&dst[n+1], w * (c[im][in][h2*2+1] + bptr[n+1]));
                }
            }
        }
    }
}

// ---------------- fp16 HMMA flash attention ---------------------------------
__global__ __launch_bounds__(256, 1) void attn_mma(
    const hf* __restrict__ QKV, hf* __restrict__ Oh)
{
    extern __shared__ hf smn[];
    uint32_t sQ = s2u(smn);              // 256*72*2 = 36864 B
    uint32_t sK = sQ + 36864;            // 9216 B
    uint32_t sV = sK + 9216;             // 9216 B; total 55296 B

    int n = blockIdx.x, h = blockIdx.y, b = blockIdx.z;
    int g = h & (Gg - 1);
    int kbase = n * (WINs / 2);
    int tid = threadIdx.x, lane = tid & 31, wid = tid >> 5;

    for (int i = tid; i < 2048; i += 256) {
        int r = i >> 3, cb = (i & 7) * 8;
        cpa16(sQ + (r * AQS + cb) * 2,
              QKV + ((size_t)(b * Ls + kbase + r)) * QKVW + h * HDd + cb);
    }
    asm volatile("cp.async.commit_group;");

    float o_acc[2][8][4] = {};
    float run_m[2][2], run_l[2][2];
    #pragma unroll
    for (int im = 0; im < 2; im++)
        #pragma unroll
        for (int rs = 0; rs < 2; rs++) { run_m[im][rs] = -1e30f; run_l[im][rs] = 0.f; }

    for (int ch = 0; ch < 4; ch++) {
        if (ch > 0) __syncthreads();
        for (int i = tid; i < 1024; i += 256) {
            int part = i >> 9;
            int r = (i >> 3) & 63, cb = (i & 7) * 8;
            int coff = (part ? 1152 : 1024) + g * HDd;
            cpa16((part ? sV : sK) + (r * AQS + cb) * 2,
                  QKV + ((size_t)(b * Ls + kbase + ch * 64 + r)) * QKVW + coff + cb);
        }
        asm volatile("cp.async.commit_group;");
        asm volatile("cp.async.wait_group 0;");
        __syncthreads();

        float s[2][8][4] = {};
        #pragma unroll
        for (int kk = 0; kk < 4; kk++) {
            uint32_t aQ[2][4], bK[8][2];
            int arow = wid * 32 + (lane & 15);
            int acol = kk * 16 + (lane >> 4) * 8;
            #pragma unroll
            for (int im = 0; im < 2; im++)
                ldsm4(aQ[im], sQ + ((arow + im * 16) * AQS + acol) * 2);
            int mtx = lane >> 3;
            int brow_off = (mtx >> 1) * 8 + (lane & 7);
            int bcol = kk * 16 + (mtx & 1) * 8;
            #pragma unroll
            for (int jp = 0; jp < 4; jp++) {
                uint32_t t4[4];
                ldsm4(t4, sK + ((jp * 16 + brow_off) * AQS + bcol) * 2);
                bK[2*jp][0] = t4[0];   bK[2*jp][1] = t4[1];
                bK[2*jp+1][0] = t4[2]; bK[2*jp+1][1] = t4[3];
            }
            #pragma unroll
            for (int im = 0; im < 2; im++)
                #pragma unroll
                for (int j = 0; j < 8; j++)
                    mma16816(s[im][j], aQ[im], bK[j]);
        }

        #pragma unroll
        for (int im = 0; im < 2; im++) {
            #pragma unroll
            for (int rs = 0; rs < 2; rs++) {
                float mx = -1e30f;
                #pragma unroll
                for (int j = 0; j < 8; j++)
                    mx = fmaxf(mx, fmaxf(s[im][j][rs*2], s[im][j][rs*2+1]));
                mx = fmaxf(mx, __shfl_xor_sync(0xffffffffu, mx, 1));
                mx = fmaxf(mx, __shfl_xor_sync(0xffffffffu, mx, 2));
                mx *= 0.125f;
                float nm = fmaxf(run_m[im][rs], mx);
                float corr = __expf(run_m[im][rs] - nm);
                run_m[im][rs] = nm;
                float rsum = 0.f;
                #pragma unroll
                for (int j = 0; j < 8; j++) {
                    float p0 = __expf(s[im][j][rs*2]   * 0.125f - nm);
                    float p1 = __expf(s[im][j][rs*2+1] * 0.125f - nm);
                    s[im][j][rs*2] = p0; s[im][j][rs*2+1] = p1;
                    rsum += p0 + p1;
                }
                rsum += __shfl_xor_sync(0xffffffffu, rsum, 1);
                rsum += __shfl_xor_sync(0xffffffffu, rsum, 2);
                run_l[im][rs] = run_l[im][rs] * corr + rsum;
                #pragma unroll
                for (int j = 0; j < 8; j++) {
                    o_acc[im][j][rs*2]   *= corr;
                    o_acc[im][j][rs*2+1] *= corr;
                }
            }
        }

        #pragma unroll
        for (int t = 0; t < 4; t++) {
            uint32_t aP[2][4];
            #pragma unroll
            for (int im = 0; im < 2; im++) {
                aP[im][0] = packhf(s[im][2*t][0],   s[im][2*t][1]);
                aP[im][1] = packhf(s[im][2*t][2],   s[im][2*t][3]);
                aP[im][2] = packhf(s[im][2*t+1][0], s[im][2*t+1][1]);
                aP[im][3] = packhf(s[im][2*t+1][2], s[im][2*t+1][3]);
            }
            uint32_t bV[8][2];
            int mtx = lane >> 3;
            int krow = t * 16 + (mtx & 1) * 8 + (lane & 7);
            int ncol = (mtx >> 1) * 8;
            #pragma unroll
            for (int jp = 0; jp < 4; jp++) {
                uint32_t t4[4];
                ldsm4t(t4, sV + (krow * AQS + jp * 16 + ncol) * 2);
                bV[2*jp][0] = t4[0];   bV[2*jp][1] = t4[1];
                bV[2*jp+1][0] = t4[2]; bV[2*jp+1][1] = t4[3];
            }
            #pragma unroll
            for (int im = 0; im < 2; im++)
                #pragma unroll
                for (int j = 0; j < 8; j++)
                    mma16816(o_acc[im][j], aP[im], bV[j]);
        }
    }

    #pragma unroll
    for (int im = 0; im < 2; im++) {
        #pragma unroll
        for (int rs = 0; rs < 2; rs++) {
            float inv = 1.f / run_l[im][rs];
            int r = wid * 32 + im * 16 + (lane >> 2) + rs * 8;
            size_t ob = ((size_t)b * Ls + n * WINs + r) * Dd + h * HDd;
            #pragma unroll
            for (int j = 0; j < 8; j++) {
                int col = j * 8 + (lane & 3) * 2;
                *(hf2*)&Oh[ob + col] = __floats2half2_rn(
                    o_acc[im][j][rs*2] * inv, o_acc[im][j][rs*2+1] * inv);
            }
        }
    }
}

// ---------------- aux scalar -------------------------------------------------
__global__ void fin_kernel(float* __restrict__ out) {
    float pen = 0.f;
    #pragma unroll
    for (int e = 0; e < Ee; e++) {
        float usage = (float)g_cnt[e] / (8192.f + 1e-8f);
        pen += fmaxf(usage - 0.4f, 0.f);
    }
    out[(size_t)NTOK * Dd] = 0.05f * (g_entsum / (float)NTOK) + pen;
}

// ---------------- launch ----------------------------------------------------
extern "C" void kernel_launch(void* const* d_in, const int* in_sizes, int n_in,
                              void* d_out, int out_size)
{
    (void)in_sizes; (void)n_in;
    const float* x    = (const float*)d_in[0];
    const float* Wq   = (const float*)d_in[1];
    const float* bq   = (const float*)d_in[2];
    const float* Wk   = (const float*)d_in[3];
    const float* bk   = (const float*)d_in[4];
    const float* Wv   = (const float*)d_in[5];
    const float* bv   = (const float*)d_in[6];
    const float* Wo   = (const float*)d_in[7];
    const float* bo   = (const float*)d_in[8];
    const float* ln1g = (const float*)d_in[9];
    const float* ln1b = (const float*)d_in[10];
    const float* ln2g = (const float*)d_in[11];
    const float* ln2b = (const float*)d_in[12];
    const float* Wg   = (const float*)d_in[13];
    const float* bg   = (const float*)d_in[14];
    const float* We   = (const float*)d_in[15];
    const float* be   = (const float*)d_in[16];
    float* out = (float*)d_out;

    float* p_bqkv;
    hf *p_qkvh, *p_a, *p_o, *p_2, *p_w, *p_wo, *p_we;
    cudaGetSymbolAddress((void**)&p_qkvh, g_qkvh);
    cudaGetSymbolAddress((void**)&p_bqkv, g_bqkv);
    cudaGetSymbolAddress((void**)&p_a,  g_a);
    cudaGetSymbolAddress((void**)&p_o,  g_o);
    cudaGetSymbolAddress((void**)&p_2,  g_2);
    cudaGetSymbolAddress((void**)&p_w,  g_w);
    cudaGetSymbolAddress((void**)&p_wo, g_wo);
    cudaGetSymbolAddress((void**)&p_we, g_we);

    const int GSMEM = NSTG * STAGEB;  // 108 KB (2 CTA/SM)
    cudaFuncSetAttribute(gemm_mma, cudaFuncAttributeMaxDynamicSharedMemorySize, GSMEM);
    const int ASMEM = 55296;          // 54 KB
    cudaFuncSetAttribute(attn_mma, cudaFuncAttributeMaxDynamicSharedMemorySize, ASMEM);

    init_kernel<<<1, 32>>>();
    catb_a<<<4, 256>>>(bq);
    catb_b<<<1, 256>>>(bk, bv);
    ln_kernel<<<NTOK, 256>>>(x, ln1g, ln1b, p_a, nullptr, nullptr);
    tconv_all<<<dim3(32, 32, 12), 256>>>(Wq, Wk, Wv, Wo, We);

    // fused QKV (fp16 out): rows < 2176 per batch, N = 1280
    gemm_mma<<<dim3(10, 17, 2), 256, GSMEM>>>(p_a, p_w, p_bqkv, nullptr,
                                              nullptr, p_qkvh, Ls, QKVW, 2);

    attn_mma<<<dim3(16, Hh, 2), 256, ASMEM>>>(p_qkvh, p_o);

    // h = x + O @ Wo + bo -> d_out
    gemm_mma<<<dim3(8, 64, 1), 256, GSMEM>>>(p_o, p_wo, bo, x, out, nullptr,
                                             0, Dd, 0);

    // ln2 + fused gating (writes g_2 fp16 + expert lists)
    ln_kernel<<<NTOK, 256>>>(out, ln2g, ln2b, p_2, Wg, bg);

    // MoE: gather tokens, atomic-scatter weighted results into out
    gemm_mma<<<dim3(8, 64, 8), 256, GSMEM>>>(p_2, p_we, be, nullptr,
                                             out, nullptr, 0, HIDs, 1);
    if (out_size > NTOK * Dd) fin_kernel<<<1, 1>>>(out);
}